// round 1
// baseline (speedup 1.0000x reference)
#include <cuda_runtime.h>
#include <math.h>

#define B_  4
#define S_  2048
#define E_  1024
#define H_  16
#define D_  64
#define T_  (B_*S_)     // 8192 tokens
#define HD_ (H_*D_)     // 1024

// Scratch (static device arrays; no runtime allocation)
__device__ float g_q[(size_t)B_*H_*S_*D_];
__device__ float g_k[(size_t)B_*H_*S_*D_];
__device__ float g_v[(size_t)B_*H_*S_*D_];
__device__ float g_o[(size_t)B_*H_*S_*D_];

// ---------------------------------------------------------------------------
// QKV projection: out[b,h,s,d] = sum_e x[t,e] * W[h,e,d] + bias[h,d]
// Treated as GEMM [T, E] x [E, H*D] with head-blocked B indexing.
// BM=BN=128, BK=16, 256 threads, 8x8 register tile per thread.
// ---------------------------------------------------------------------------
__global__ __launch_bounds__(256) void qkv_kernel(
    const float* __restrict__ x,      // [T, E]
    const float* __restrict__ W,      // [H, E, D]
    const float* __restrict__ bias,   // [H*D]
    float* __restrict__ out)          // [B,H,S,D]
{
    const int BM = 128, BN = 128, BK = 16;
    __shared__ float As[BK][BM + 4];  // transposed: As[k][m]
    __shared__ float Bs[BK][BN + 4];

    int tid = threadIdx.x;
    int ty = tid >> 4, tx = tid & 15;
    int m0 = blockIdx.x * BM;
    int n0 = blockIdx.y * BN;

    float acc[8][8];
    #pragma unroll
    for (int i = 0; i < 8; i++)
        #pragma unroll
        for (int j = 0; j < 8; j++) acc[i][j] = 0.f;

    for (int kb = 0; kb < E_; kb += BK) {
        // Load A tile (x) — float4 along e
        #pragma unroll
        for (int it = 0; it < 2; it++) {
            int p = tid + it * 256;          // 0..511 float4 slots
            int m = p >> 2;                  // 0..127
            int kg = (p & 3) * 4;            // 0,4,8,12
            float4 va = *(const float4*)(x + (size_t)(m0 + m) * E_ + kb + kg);
            As[kg + 0][m] = va.x;
            As[kg + 1][m] = va.y;
            As[kg + 2][m] = va.z;
            As[kg + 3][m] = va.w;
        }
        // Load B tile (W, head-blocked): B[e][n] = W[(n>>6)*E*D + e*D + (n&63)]
        #pragma unroll
        for (int it = 0; it < 2; it++) {
            int p = tid + it * 256;
            int k = p >> 5;                  // 0..15
            int nc = (p & 31) * 4;           // 0..124
            int n = n0 + nc;
            const float* src = W + (size_t)(n >> 6) * (E_ * D_)
                                 + (size_t)(kb + k) * D_ + (n & 63);
            *(float4*)&Bs[k][nc] = *(const float4*)src;
        }
        __syncthreads();

        #pragma unroll
        for (int k = 0; k < BK; k++) {
            float af[8], bf[8];
            *(float4*)&af[0] = *(const float4*)&As[k][ty * 8];
            *(float4*)&af[4] = *(const float4*)&As[k][ty * 8 + 4];
            *(float4*)&bf[0] = *(const float4*)&Bs[k][tx * 8];
            *(float4*)&bf[4] = *(const float4*)&Bs[k][tx * 8 + 4];
            #pragma unroll
            for (int i = 0; i < 8; i++)
                #pragma unroll
                for (int j = 0; j < 8; j++)
                    acc[i][j] += af[i] * bf[j];
        }
        __syncthreads();
    }

    // Epilogue: write to [B,H,S,D] layout with bias
    #pragma unroll
    for (int i = 0; i < 8; i++) {
        int t = m0 + ty * 8 + i;
        int b = t >> 11;           // /S_
        int s = t & 2047;
        #pragma unroll
        for (int j = 0; j < 8; j++) {
            int n = n0 + tx * 8 + j;
            int h = n >> 6, d = n & 63;
            out[(((size_t)(b * H_ + h)) * S_ + s) * D_ + d] = acc[i][j] + bias[n];
        }
    }
}

// ---------------------------------------------------------------------------
// Output projection: y[t,e] = sum_c ctx[t,c] * Wp[c,e] + bp[e]
// ctx[t,c] lives in g_o with [B,H,S,D] layout (c = h*64 + d).
// ---------------------------------------------------------------------------
__global__ __launch_bounds__(256) void proj_kernel(
    const float* __restrict__ ctx,    // g_o, [B,H,S,D]
    const float* __restrict__ Wp,     // [HD, E]
    const float* __restrict__ bp,     // [E]
    float* __restrict__ out)          // [T, E]
{
    const int BM = 128, BN = 128, BK = 16;
    __shared__ float As[BK][BM + 4];
    __shared__ float Bs[BK][BN + 4];

    int tid = threadIdx.x;
    int ty = tid >> 4, tx = tid & 15;
    int m0 = blockIdx.x * BM;
    int n0 = blockIdx.y * BN;

    float acc[8][8];
    #pragma unroll
    for (int i = 0; i < 8; i++)
        #pragma unroll
        for (int j = 0; j < 8; j++) acc[i][j] = 0.f;

    for (int kb = 0; kb < HD_; kb += BK) {
        #pragma unroll
        for (int it = 0; it < 2; it++) {
            int p = tid + it * 256;
            int m = p >> 2;
            int kg = (p & 3) * 4;
            int t = m0 + m;
            int c = kb + kg;
            const float* src = ctx + (((size_t)(t >> 11) * H_ + (c >> 6)) * S_
                                      + (t & 2047)) * D_ + (c & 63);
            float4 va = *(const float4*)src;
            As[kg + 0][m] = va.x;
            As[kg + 1][m] = va.y;
            As[kg + 2][m] = va.z;
            As[kg + 3][m] = va.w;
        }
        #pragma unroll
        for (int it = 0; it < 2; it++) {
            int p = tid + it * 256;
            int k = p >> 5;
            int nc = (p & 31) * 4;
            *(float4*)&Bs[k][nc] =
                *(const float4*)(Wp + (size_t)(kb + k) * E_ + n0 + nc);
        }
        __syncthreads();

        #pragma unroll
        for (int k = 0; k < BK; k++) {
            float af[8], bf[8];
            *(float4*)&af[0] = *(const float4*)&As[k][ty * 8];
            *(float4*)&af[4] = *(const float4*)&As[k][ty * 8 + 4];
            *(float4*)&bf[0] = *(const float4*)&Bs[k][tx * 8];
            *(float4*)&bf[4] = *(const float4*)&Bs[k][tx * 8 + 4];
            #pragma unroll
            for (int i = 0; i < 8; i++)
                #pragma unroll
                for (int j = 0; j < 8; j++)
                    acc[i][j] += af[i] * bf[j];
        }
        __syncthreads();
    }

    #pragma unroll
    for (int i = 0; i < 8; i++) {
        int t = m0 + ty * 8 + i;
        #pragma unroll
        for (int j = 0; j < 8; j++) {
            int n = n0 + tx * 8 + j;
            out[(size_t)t * E_ + n] = acc[i][j] + bp[n];
        }
    }
}

// ---------------------------------------------------------------------------
// Flash attention (fp32, causal). One CTA per (b*h, q-tile of 64 rows).
// BQ = BKV = 64, D = 64. 256 threads, 4x4 register microtiles.
// Dynamic smem: Qs[64][68] + Kst[64][68] (transposed) + Vs[64][68] + Ss[64][68]
//               + mrow/lrow/arow[64]  = 70,400 bytes
// ---------------------------------------------------------------------------
#define AT_STR 68
#define ATTN_SMEM ((4 * 64 * AT_STR + 3 * 64) * 4)

__global__ __launch_bounds__(256) void attn_kernel(
    const float* __restrict__ q,
    const float* __restrict__ k,
    const float* __restrict__ v,
    float* __restrict__ o)
{
    extern __shared__ float sm[];
    float* Qs  = sm;                    // [64][68]  Qs[i][d]
    float* Kst = Qs  + 64 * AT_STR;     // [64][68]  Kst[d][j]
    float* Vs  = Kst + 64 * AT_STR;     // [64][68]  Vs[j][d]
    float* Ss  = Vs  + 64 * AT_STR;     // [64][68]  Ss[i][j]
    float* mrow = Ss + 64 * AT_STR;     // [64]
    float* lrow = mrow + 64;            // [64]
    float* arow = lrow + 64;            // [64]

    int tid = threadIdx.x;
    int ty = tid >> 4, tx = tid & 15;
    int lane = tid & 31, wrp = tid >> 5;
    int q0 = blockIdx.x * 64;
    int bh = blockIdx.y;

    const float* qb = q + (size_t)bh * S_ * D_;
    const float* kb = k + (size_t)bh * S_ * D_;
    const float* vb = v + (size_t)bh * S_ * D_;

    // Load Q tile
    #pragma unroll
    for (int it = 0; it < 4; it++) {
        int p = tid + it * 256;           // float4 slot, 0..1023
        int r = p >> 4;                   // row 0..63
        int dc = (p & 15) * 4;            // 0..60
        *(float4*)&Qs[r * AT_STR + dc] =
            *(const float4*)(qb + (size_t)(q0 + r) * D_ + dc);
    }
    if (tid < 64) { mrow[tid] = -1e30f; lrow[tid] = 0.f; }

    float Oacc[4][4];
    #pragma unroll
    for (int r = 0; r < 4; r++)
        #pragma unroll
        for (int c = 0; c < 4; c++) Oacc[r][c] = 0.f;

    __syncthreads();

    for (int j0 = 0; j0 <= q0; j0 += 64) {
        // Load K (transposed) and V tiles
        #pragma unroll
        for (int it = 0; it < 4; it++) {
            int p = tid + it * 256;
            int r = p >> 4;
            int dc = (p & 15) * 4;
            float4 vk = *(const float4*)(kb + (size_t)(j0 + r) * D_ + dc);
            Kst[(dc + 0) * AT_STR + r] = vk.x;
            Kst[(dc + 1) * AT_STR + r] = vk.y;
            Kst[(dc + 2) * AT_STR + r] = vk.z;
            Kst[(dc + 3) * AT_STR + r] = vk.w;
            *(float4*)&Vs[r * AT_STR + dc] =
                *(const float4*)(vb + (size_t)(j0 + r) * D_ + dc);
        }
        __syncthreads();

        // Scores: sc[r][c] = sum_d Q[ty*4+r][d] * K[tx*4+c][d]
        float sc[4][4];
        #pragma unroll
        for (int r = 0; r < 4; r++)
            #pragma unroll
            for (int c = 0; c < 4; c++) sc[r][c] = 0.f;

        #pragma unroll 8
        for (int d = 0; d < 64; d++) {
            float4 kf = *(const float4*)&Kst[d * AT_STR + tx * 4];
            #pragma unroll
            for (int r = 0; r < 4; r++) {
                float qv = Qs[(ty * 4 + r) * AT_STR + d];
                sc[r][0] += qv * kf.x;
                sc[r][1] += qv * kf.y;
                sc[r][2] += qv * kf.z;
                sc[r][3] += qv * kf.w;
            }
        }

        // Scale + causal mask (only diagonal tile can mask), write to Ss
        bool diag = (j0 == q0);
        #pragma unroll
        for (int r = 0; r < 4; r++) {
            int gi = q0 + ty * 4 + r;
            #pragma unroll
            for (int c = 0; c < 4; c++) {
                int gj = j0 + tx * 4 + c;
                float sv = sc[r][c] * 0.125f;
                if (diag && gj > gi) sv = -1e30f;
                Ss[(ty * 4 + r) * AT_STR + tx * 4 + c] = sv;
            }
        }
        __syncthreads();

        // Online softmax: warp per row (8 warps x 8 rows)
        #pragma unroll
        for (int rr = 0; rr < 8; rr++) {
            int row = wrp * 8 + rr;
            float v0 = Ss[row * AT_STR + lane];
            float v1 = Ss[row * AT_STR + 32 + lane];
            float mx = fmaxf(v0, v1);
            #pragma unroll
            for (int off = 16; off > 0; off >>= 1)
                mx = fmaxf(mx, __shfl_xor_sync(0xffffffffu, mx, off));
            float mold = mrow[row];
            float mnew = fmaxf(mold, mx);
            float p0 = __expf(v0 - mnew);
            float p1 = __expf(v1 - mnew);
            Ss[row * AT_STR + lane] = p0;
            Ss[row * AT_STR + 32 + lane] = p1;
            float sum = p0 + p1;
            #pragma unroll
            for (int off = 16; off > 0; off >>= 1)
                sum += __shfl_xor_sync(0xffffffffu, sum, off);
            if (lane == 0) {
                float alpha = __expf(mold - mnew);
                arow[row] = alpha;
                lrow[row] = lrow[row] * alpha + sum;
                mrow[row] = mnew;
            }
        }
        __syncthreads();

        // O update: O = O*alpha + P @ V
        float a[4];
        #pragma unroll
        for (int r = 0; r < 4; r++) a[r] = arow[ty * 4 + r];
        #pragma unroll
        for (int r = 0; r < 4; r++)
            #pragma unroll
            for (int c = 0; c < 4; c++) Oacc[r][c] *= a[r];

        #pragma unroll 8
        for (int j = 0; j < 64; j++) {
            float4 vf = *(const float4*)&Vs[j * AT_STR + tx * 4];
            #pragma unroll
            for (int r = 0; r < 4; r++) {
                float pv = Ss[(ty * 4 + r) * AT_STR + j];
                Oacc[r][0] += pv * vf.x;
                Oacc[r][1] += pv * vf.y;
                Oacc[r][2] += pv * vf.z;
                Oacc[r][3] += pv * vf.w;
            }
        }
        __syncthreads();   // protect Kst/Vs/Ss before next tile load
    }

    // Finalize: divide by l, write out [B,H,S,D]
    #pragma unroll
    for (int r = 0; r < 4; r++) {
        int i = ty * 4 + r;
        float inv = 1.f / lrow[i];
        float4 res;
        res.x = Oacc[r][0] * inv;
        res.y = Oacc[r][1] * inv;
        res.z = Oacc[r][2] * inv;
        res.w = Oacc[r][3] * inv;
        *(float4*)(o + ((size_t)bh * S_ + (q0 + i)) * D_ + tx * 4) = res;
    }
}

// ---------------------------------------------------------------------------
extern "C" void kernel_launch(void* const* d_in, const int* in_sizes, int n_in,
                              void* d_out, int out_size)
{
    const float* x  = (const float*)d_in[0];
    const float* Wq = (const float*)d_in[1];
    const float* bq = (const float*)d_in[2];
    const float* Wk = (const float*)d_in[3];
    const float* bk = (const float*)d_in[4];
    const float* Wv = (const float*)d_in[5];
    const float* bv = (const float*)d_in[6];
    const float* Wp = (const float*)d_in[7];
    const float* bp = (const float*)d_in[8];
    float* out = (float*)d_out;

    float *qp, *kp, *vp, *op;
    cudaGetSymbolAddress((void**)&qp, g_q);
    cudaGetSymbolAddress((void**)&kp, g_k);
    cudaGetSymbolAddress((void**)&vp, g_v);
    cudaGetSymbolAddress((void**)&op, g_o);

    cudaFuncSetAttribute(attn_kernel,
                         cudaFuncAttributeMaxDynamicSharedMemorySize, ATTN_SMEM);

    dim3 gproj(T_ / 128, HD_ / 128);   // 64 x 8
    qkv_kernel<<<gproj, 256>>>(x, Wq, bq, qp);
    qkv_kernel<<<gproj, 256>>>(x, Wk, bk, kp);
    qkv_kernel<<<gproj, 256>>>(x, Wv, bv, vp);

    dim3 gattn(S_ / 64, B_ * H_);      // 32 x 64
    attn_kernel<<<gattn, 256, ATTN_SMEM>>>(qp, kp, vp, op);

    dim3 gout(T_ / 128, E_ / 128);     // 64 x 8
    proj_kernel<<<gout, 256>>>(op, Wp, bp, out);
}

// round 3
// speedup vs baseline: 2.0960x; 2.0960x over previous
#include <cuda_runtime.h>
#include <cstdint>
#include <math.h>

#define B_  4
#define S_  2048
#define E_  1024
#define H_  16
#define D_  64
#define T_  (B_*S_)     // 8192 tokens
#define HD_ (H_*D_)     // 1024

// ---------------------------------------------------------------------------
// Scratch (static device arrays; no runtime allocation)
// ---------------------------------------------------------------------------
__device__ float g_q[(size_t)B_*H_*S_*D_];   // [B,H,S,D]
__device__ float g_k[(size_t)B_*H_*S_*D_];
__device__ float g_v[(size_t)B_*H_*S_*D_];
__device__ float g_o[(size_t)T_*HD_];        // [B,S,H,D] == [T, HD]
__device__ float g_wqt[(size_t)HD_*E_];      // K-major: [n=h*64+d][e]
__device__ float g_wkt[(size_t)HD_*E_];
__device__ float g_wvt[(size_t)HD_*E_];
__device__ float g_wpt[(size_t)E_*HD_];      // K-major: [n=e][c]

// ---------------------------------------------------------------------------
// PTX helpers (plain sm_103-target-safe: mma.sync + cp.async only)
// ---------------------------------------------------------------------------
__device__ __forceinline__ uint32_t smem_u32(const void* p) {
    return (uint32_t)__cvta_generic_to_shared(p);
}
__device__ __forceinline__ void cp_async16(uint32_t dst, const void* src) {
    asm volatile("cp.async.cg.shared.global [%0], [%1], 16;\n" :: "r"(dst), "l"(src));
}
__device__ __forceinline__ void cp_commit() {
    asm volatile("cp.async.commit_group;\n" ::: "memory");
}
template<int N> __device__ __forceinline__ void cp_wait() {
    asm volatile("cp.async.wait_group %0;\n" :: "n"(N) : "memory");
}
__device__ __forceinline__ uint32_t f2tf(float x) {
    uint32_t r;
    asm("cvt.rna.tf32.f32 %0, %1;" : "=r"(r) : "f"(x));
    return r;
}
__device__ __forceinline__ void mma_tf32(float* c,
    uint32_t a0, uint32_t a1, uint32_t a2, uint32_t a3,
    uint32_t b0, uint32_t b1)
{
    asm volatile(
        "mma.sync.aligned.m16n8k8.row.col.f32.tf32.tf32.f32 "
        "{%0,%1,%2,%3},{%4,%5,%6,%7},{%8,%9},{%0,%1,%2,%3};"
        : "+f"(c[0]), "+f"(c[1]), "+f"(c[2]), "+f"(c[3])
        : "r"(a0), "r"(a1), "r"(a2), "r"(a3), "r"(b0), "r"(b1));
}

// ---------------------------------------------------------------------------
// Weight transpose: per-batch [R, C] -> [C, R] (batch stride R*C on both sides)
// ---------------------------------------------------------------------------
__global__ void transpose_kernel(const float* __restrict__ src,
                                 float* __restrict__ dst, int R, int C)
{
    __shared__ float tile[32][33];
    const float* s = src + (size_t)blockIdx.z * R * C;
    float* d = dst + (size_t)blockIdx.z * R * C;
    int r0 = blockIdx.y * 32, c0 = blockIdx.x * 32;
    #pragma unroll
    for (int i = threadIdx.y; i < 32; i += 8)
        tile[i][threadIdx.x] = s[(size_t)(r0 + i) * C + c0 + threadIdx.x];
    __syncthreads();
    #pragma unroll
    for (int i = threadIdx.y; i < 32; i += 8)
        d[(size_t)(c0 + i) * R + r0 + threadIdx.x] = tile[threadIdx.x][i];
}

// ---------------------------------------------------------------------------
// tf32 mma.sync GEMM: out = A[8192,1024] x Bw^T (+bias), Bw K-major [N,K]
// CTA 128x128, BK=32, 4-stage cp.async pipeline, 8 warps (4m x 2n),
// warp tile 32x64, fragments m16n8k8 (MF=2, NF=8).
// MODE 0: out is q/k/v [B,H,S,D] (n = h*64+d).  MODE 1: out is [T, E].
// ---------------------------------------------------------------------------
#define GEMM_BK     32
#define GEMM_STAGES 4
#define GEMM_KT     (E_ / GEMM_BK)            // 32
#define GEMM_LDS    36                        // floats per row (32 + 4 pad)
#define GEMM_TILE   (128 * GEMM_LDS)          // floats per tile
#define GEMM_STAGEF (2 * GEMM_TILE)           // floats per stage (A + B)
#define GEMM_SMEM   (GEMM_STAGES * GEMM_STAGEF * 4)

__device__ __forceinline__ void gemm_load_stage(
    const float* __restrict__ Ag, const float* __restrict__ Bg,
    uint32_t abase, uint32_t bbase, int tid)
{
    // 128 rows x 8 chunks(16B) = 1024 chunks per tile; 256 threads -> 4 each
    #pragma unroll
    for (int j = 0; j < 4; j++) {
        int p = tid + j * 256;
        int r = p >> 3;                 // 0..127
        int ch = p & 7;                 // 0..7
        uint32_t off = (uint32_t)(r * (GEMM_LDS * 4) + ch * 16);
        cp_async16(abase + off, (const char*)Ag + (size_t)r * (E_ * 4) + ch * 16);
        cp_async16(bbase + off, (const char*)Bg + (size_t)r * (E_ * 4) + ch * 16);
    }
}

template<int MODE>
__global__ __launch_bounds__(256) void gemm_mma(
    const float* __restrict__ A,     // [8192, 1024] K-contiguous
    const float* __restrict__ Bw,    // [1024, 1024] K-contiguous (n rows)
    const float* __restrict__ bias,  // [1024]
    float* __restrict__ out)
{
    extern __shared__ __align__(16) float smem[];
    uint32_t sb = smem_u32(smem);

    int tid = threadIdx.x;
    int wid = tid >> 5, lane = tid & 31;
    int g = lane >> 2, c = lane & 3;
    int wm = wid & 3, wn = wid >> 2;          // 4 x 2 warp grid
    int m0 = blockIdx.x * 128;
    int n0 = blockIdx.y * 128;

    const float* Abase = A + (size_t)m0 * E_;
    const float* Bbase = Bw + (size_t)n0 * E_;

    float cfr[2][8][4];
    #pragma unroll
    for (int mf = 0; mf < 2; mf++)
        #pragma unroll
        for (int nf = 0; nf < 8; nf++)
            #pragma unroll
            for (int i = 0; i < 4; i++) cfr[mf][nf][i] = 0.f;

    // Prologue: fill first 3 stages
    #pragma unroll
    for (int s = 0; s < GEMM_STAGES - 1; s++) {
        gemm_load_stage(Abase + s * GEMM_BK, Bbase + s * GEMM_BK,
                        sb + s * GEMM_STAGEF * 4,
                        sb + (s * GEMM_STAGEF + GEMM_TILE) * 4, tid);
        cp_commit();
    }

    for (int kt = 0; kt < GEMM_KT; kt++) {
        cp_wait<GEMM_STAGES - 2>();
        __syncthreads();

        int s = kt & (GEMM_STAGES - 1);
        const float* As = smem + s * GEMM_STAGEF;
        const float* Bs = As + GEMM_TILE;

        #pragma unroll
        for (int ks = 0; ks < 4; ks++) {
            int k0 = ks * 8;
            uint32_t a[2][4];
            #pragma unroll
            for (int mf = 0; mf < 2; mf++) {
                int r = wm * 32 + mf * 16 + g;
                a[mf][0] = f2tf(As[r * GEMM_LDS + k0 + c]);
                a[mf][1] = f2tf(As[(r + 8) * GEMM_LDS + k0 + c]);
                a[mf][2] = f2tf(As[r * GEMM_LDS + k0 + c + 4]);
                a[mf][3] = f2tf(As[(r + 8) * GEMM_LDS + k0 + c + 4]);
            }
            #pragma unroll
            for (int nf = 0; nf < 8; nf++) {
                int n = wn * 64 + nf * 8 + g;
                uint32_t b0 = f2tf(Bs[n * GEMM_LDS + k0 + c]);
                uint32_t b1 = f2tf(Bs[n * GEMM_LDS + k0 + c + 4]);
                mma_tf32(cfr[0][nf], a[0][0], a[0][1], a[0][2], a[0][3], b0, b1);
                mma_tf32(cfr[1][nf], a[1][0], a[1][1], a[1][2], a[1][3], b0, b1);
            }
        }

        int ktn = kt + GEMM_STAGES - 1;
        if (ktn < GEMM_KT) {
            int sn = ktn & (GEMM_STAGES - 1);
            gemm_load_stage(Abase + ktn * GEMM_BK, Bbase + ktn * GEMM_BK,
                            sb + sn * GEMM_STAGEF * 4,
                            sb + (sn * GEMM_STAGEF + GEMM_TILE) * 4, tid);
        }
        cp_commit();
    }

    // Epilogue
    #pragma unroll
    for (int mf = 0; mf < 2; mf++) {
        #pragma unroll
        for (int half = 0; half < 2; half++) {
            int row = wm * 32 + mf * 16 + g + half * 8;
            int t = m0 + row;
            #pragma unroll
            for (int nf = 0; nf < 8; nf++) {
                int col = n0 + wn * 64 + nf * 8 + 2 * c;
                float2 v;
                v.x = cfr[mf][nf][2 * half + 0] + bias[col];
                v.y = cfr[mf][nf][2 * half + 1] + bias[col + 1];
                if (MODE == 0) {
                    int b = t >> 11, s_ = t & 2047;
                    int h = col >> 6, d0 = col & 63;
                    *(float2*)(out + (((size_t)(b * H_ + h)) * S_ + s_) * D_ + d0) = v;
                } else {
                    *(float2*)(out + (size_t)t * E_ + col) = v;
                }
            }
        }
    }
}

// ---------------------------------------------------------------------------
// Flash attention (tf32 mma.sync, causal). One CTA per (b*h, q-tile of 64).
// 256 threads = 8 warps (2m x 4n for the MMAs), SIMT softmax between MMAs.
// Output layout [B,S,H,D].
// ---------------------------------------------------------------------------
#define AT_STR 68
#define ATTN_SMEM ((4 * 64 * AT_STR + 3 * 64) * 4)

__global__ __launch_bounds__(256) void attn_kernel(
    const float* __restrict__ q,
    const float* __restrict__ k,
    const float* __restrict__ v,
    float* __restrict__ o)
{
    extern __shared__ float sm[];
    float* Qs  = sm;                    // [64][68]  Qs[i][d]
    float* Kst = Qs  + 64 * AT_STR;     // [68*64]   Kst[d][j] (d-major)
    float* Vs  = Kst + 64 * AT_STR;     // [64][68]  Vs[j][d]
    float* Ss  = Vs  + 64 * AT_STR;     // [64][68]  scores -> P
    float* mrow = Ss + 64 * AT_STR;
    float* lrow = mrow + 64;
    float* arow = lrow + 64;

    int tid = threadIdx.x;
    int lane = tid & 31, wid = tid >> 5;
    int g = lane >> 2, c = lane & 3;
    int wm = wid & 1, wn = wid >> 1;    // 2 x 4 warp grid (32m x 16n tiles)
    int q0 = blockIdx.x * 64;
    int bh = blockIdx.y;

    const float* qb = q + (size_t)bh * S_ * D_;
    const float* kb = k + (size_t)bh * S_ * D_;
    const float* vb = v + (size_t)bh * S_ * D_;

    // Load Q tile
    #pragma unroll
    for (int it = 0; it < 4; it++) {
        int p = tid + it * 256;
        int r = p >> 4;
        int dc = (p & 15) * 4;
        *(float4*)&Qs[r * AT_STR + dc] =
            *(const float4*)(qb + (size_t)(q0 + r) * D_ + dc);
    }
    if (tid < 64) { mrow[tid] = -1e30f; lrow[tid] = 0.f; }

    float ofr[2][2][4];
    #pragma unroll
    for (int mf = 0; mf < 2; mf++)
        #pragma unroll
        for (int nf = 0; nf < 2; nf++)
            #pragma unroll
            for (int i = 0; i < 4; i++) ofr[mf][nf][i] = 0.f;

    __syncthreads();

    for (int j0 = 0; j0 <= q0; j0 += 64) {
        // Load K (transposed -> Kst[d][j]) and V (Vs[j][d])
        #pragma unroll
        for (int it = 0; it < 4; it++) {
            int p = tid + it * 256;
            int r = p >> 4;
            int dc = (p & 15) * 4;
            float4 vk = *(const float4*)(kb + (size_t)(j0 + r) * D_ + dc);
            Kst[(dc + 0) * AT_STR + r] = vk.x;
            Kst[(dc + 1) * AT_STR + r] = vk.y;
            Kst[(dc + 2) * AT_STR + r] = vk.z;
            Kst[(dc + 3) * AT_STR + r] = vk.w;
            *(float4*)&Vs[r * AT_STR + dc] =
                *(const float4*)(vb + (size_t)(j0 + r) * D_ + dc);
        }
        __syncthreads();

        // S = Q @ K^T via mma (m64 n64 k64)
        float sfr[2][2][4];
        #pragma unroll
        for (int mf = 0; mf < 2; mf++)
            #pragma unroll
            for (int nf = 0; nf < 2; nf++)
                #pragma unroll
                for (int i = 0; i < 4; i++) sfr[mf][nf][i] = 0.f;

        #pragma unroll
        for (int kk = 0; kk < 8; kk++) {
            int k0 = kk * 8;
            uint32_t a[2][4];
            #pragma unroll
            for (int mf = 0; mf < 2; mf++) {
                int r = wm * 32 + mf * 16 + g;
                a[mf][0] = f2tf(Qs[r * AT_STR + k0 + c]);
                a[mf][1] = f2tf(Qs[(r + 8) * AT_STR + k0 + c]);
                a[mf][2] = f2tf(Qs[r * AT_STR + k0 + c + 4]);
                a[mf][3] = f2tf(Qs[(r + 8) * AT_STR + k0 + c + 4]);
            }
            #pragma unroll
            for (int nf = 0; nf < 2; nf++) {
                int n = wn * 16 + nf * 8 + g;
                uint32_t b0 = f2tf(Kst[(k0 + c) * AT_STR + n]);
                uint32_t b1 = f2tf(Kst[(k0 + c + 4) * AT_STR + n]);
                mma_tf32(sfr[0][nf], a[0][0], a[0][1], a[0][2], a[0][3], b0, b1);
                mma_tf32(sfr[1][nf], a[1][0], a[1][1], a[1][2], a[1][3], b0, b1);
            }
        }

        // Scale + causal mask + store scores to smem
        bool diag = (j0 == q0);
        #pragma unroll
        for (int mf = 0; mf < 2; mf++) {
            #pragma unroll
            for (int nf = 0; nf < 2; nf++) {
                int col = wn * 16 + nf * 8 + 2 * c;
                #pragma unroll
                for (int half = 0; half < 2; half++) {
                    int row = wm * 32 + mf * 16 + g + half * 8;
                    int gi = q0 + row;
                    float v0 = sfr[mf][nf][2 * half + 0] * 0.125f;
                    float v1 = sfr[mf][nf][2 * half + 1] * 0.125f;
                    if (diag) {
                        if (j0 + col > gi) v0 = -1e30f;
                        if (j0 + col + 1 > gi) v1 = -1e30f;
                    }
                    float2 sv; sv.x = v0; sv.y = v1;
                    *(float2*)&Ss[row * AT_STR + col] = sv;
                }
            }
        }
        __syncthreads();

        // Online softmax: warp per row (8 warps x 8 rows)
        #pragma unroll
        for (int rr = 0; rr < 8; rr++) {
            int row = wid * 8 + rr;
            float v0 = Ss[row * AT_STR + lane];
            float v1 = Ss[row * AT_STR + 32 + lane];
            float mx = fmaxf(v0, v1);
            #pragma unroll
            for (int off = 16; off > 0; off >>= 1)
                mx = fmaxf(mx, __shfl_xor_sync(0xffffffffu, mx, off));
            float mold = mrow[row];
            float mnew = fmaxf(mold, mx);
            float p0 = __expf(v0 - mnew);
            float p1 = __expf(v1 - mnew);
            Ss[row * AT_STR + lane] = p0;
            Ss[row * AT_STR + 32 + lane] = p1;
            float sum = p0 + p1;
            #pragma unroll
            for (int off = 16; off > 0; off >>= 1)
                sum += __shfl_xor_sync(0xffffffffu, sum, off);
            if (lane == 0) {
                float alpha = __expf(mold - mnew);
                arow[row] = alpha;
                lrow[row] = lrow[row] * alpha + sum;
                mrow[row] = mnew;
            }
        }
        __syncthreads();

        // O = O*alpha + P @ V via mma
        #pragma unroll
        for (int mf = 0; mf < 2; mf++) {
            int r = wm * 32 + mf * 16 + g;
            float al0 = arow[r];
            float al1 = arow[r + 8];
            #pragma unroll
            for (int nf = 0; nf < 2; nf++) {
                ofr[mf][nf][0] *= al0;
                ofr[mf][nf][1] *= al0;
                ofr[mf][nf][2] *= al1;
                ofr[mf][nf][3] *= al1;
            }
        }

        #pragma unroll
        for (int kk = 0; kk < 8; kk++) {
            int k0 = kk * 8;
            uint32_t a[2][4];
            #pragma unroll
            for (int mf = 0; mf < 2; mf++) {
                int r = wm * 32 + mf * 16 + g;
                a[mf][0] = f2tf(Ss[r * AT_STR + k0 + c]);
                a[mf][1] = f2tf(Ss[(r + 8) * AT_STR + k0 + c]);
                a[mf][2] = f2tf(Ss[r * AT_STR + k0 + c + 4]);
                a[mf][3] = f2tf(Ss[(r + 8) * AT_STR + k0 + c + 4]);
            }
            #pragma unroll
            for (int nf = 0; nf < 2; nf++) {
                int n = wn * 16 + nf * 8 + g;
                uint32_t b0 = f2tf(Vs[(k0 + c) * AT_STR + n]);
                uint32_t b1 = f2tf(Vs[(k0 + c + 4) * AT_STR + n]);
                mma_tf32(ofr[0][nf], a[0][0], a[0][1], a[0][2], a[0][3], b0, b1);
                mma_tf32(ofr[1][nf], a[1][0], a[1][1], a[1][2], a[1][3], b0, b1);
            }
        }
        __syncthreads();   // protect Kst/Vs/Ss before next tile load
    }

    // Finalize: divide by l, write out [B,S,H,D]
    int b = bh >> 4, h = bh & 15;
    #pragma unroll
    for (int mf = 0; mf < 2; mf++) {
        #pragma unroll
        for (int half = 0; half < 2; half++) {
            int row = wm * 32 + mf * 16 + g + half * 8;
            float inv = 1.f / lrow[row];
            size_t base = (((size_t)b * S_ + (q0 + row)) * H_ + h) * D_;
            #pragma unroll
            for (int nf = 0; nf < 2; nf++) {
                int col = wn * 16 + nf * 8 + 2 * c;
                float2 res;
                res.x = ofr[mf][nf][2 * half + 0] * inv;
                res.y = ofr[mf][nf][2 * half + 1] * inv;
                *(float2*)(o + base + col) = res;
            }
        }
    }
}

// ---------------------------------------------------------------------------
extern "C" void kernel_launch(void* const* d_in, const int* in_sizes, int n_in,
                              void* d_out, int out_size)
{
    const float* x  = (const float*)d_in[0];
    const float* Wq = (const float*)d_in[1];
    const float* bq = (const float*)d_in[2];
    const float* Wk = (const float*)d_in[3];
    const float* bk = (const float*)d_in[4];
    const float* Wv = (const float*)d_in[5];
    const float* bv = (const float*)d_in[6];
    const float* Wp = (const float*)d_in[7];
    const float* bp = (const float*)d_in[8];
    float* out = (float*)d_out;

    float *qp, *kp, *vp, *op, *wqt, *wkt, *wvt, *wpt;
    cudaGetSymbolAddress((void**)&qp, g_q);
    cudaGetSymbolAddress((void**)&kp, g_k);
    cudaGetSymbolAddress((void**)&vp, g_v);
    cudaGetSymbolAddress((void**)&op, g_o);
    cudaGetSymbolAddress((void**)&wqt, g_wqt);
    cudaGetSymbolAddress((void**)&wkt, g_wkt);
    cudaGetSymbolAddress((void**)&wvt, g_wvt);
    cudaGetSymbolAddress((void**)&wpt, g_wpt);

    cudaFuncSetAttribute(attn_kernel,
                         cudaFuncAttributeMaxDynamicSharedMemorySize, ATTN_SMEM);
    cudaFuncSetAttribute(gemm_mma<0>,
                         cudaFuncAttributeMaxDynamicSharedMemorySize, GEMM_SMEM);
    cudaFuncSetAttribute(gemm_mma<1>,
                         cudaFuncAttributeMaxDynamicSharedMemorySize, GEMM_SMEM);

    // Transpose weights to K-major
    dim3 tb(32, 8);
    dim3 tgw(D_ / 32, E_ / 32, H_);                  // W[h]: [E,D] -> [D,E]
    transpose_kernel<<<tgw, tb>>>(Wq, wqt, E_, D_);
    transpose_kernel<<<tgw, tb>>>(Wk, wkt, E_, D_);
    transpose_kernel<<<tgw, tb>>>(Wv, wvt, E_, D_);
    dim3 tgp(E_ / 32, HD_ / 32, 1);                  // Wp: [HD,E] -> [E,HD]
    transpose_kernel<<<tgp, tb>>>(Wp, wpt, HD_, E_);

    // QKV projections (tf32 mma.sync)
    dim3 gg(T_ / 128, HD_ / 128);                    // 64 x 8
    gemm_mma<0><<<gg, 256, GEMM_SMEM>>>(x, wqt, bq, qp);
    gemm_mma<0><<<gg, 256, GEMM_SMEM>>>(x, wkt, bk, kp);
    gemm_mma<0><<<gg, 256, GEMM_SMEM>>>(x, wvt, bv, vp);

    // Attention (tf32 mma.sync + SIMT online softmax)
    dim3 gattn(S_ / 64, B_ * H_);                    // 32 x 64
    attn_kernel<<<gattn, 256, ATTN_SMEM>>>(qp, kp, vp, op);

    // Output projection (tf32 mma.sync)
    dim3 gp(T_ / 128, E_ / 128);
    gemm_mma<1><<<gp, 256, GEMM_SMEM>>>(op, wpt, bp, out);
}

// round 4
// speedup vs baseline: 2.6986x; 1.2875x over previous
#include <cuda_runtime.h>
#include <cstdint>
#include <math.h>

#define B_  4
#define S_  2048
#define E_  1024
#define H_  16
#define D_  64
#define T_  (B_*S_)     // 8192 tokens
#define HD_ (H_*D_)     // 1024

// ---------------------------------------------------------------------------
// Scratch (static device arrays; no runtime allocation)
// ---------------------------------------------------------------------------
__device__ float g_x[(size_t)T_*E_];          // tf32-rounded x
__device__ float g_qkv[(size_t)3*T_*HD_];     // q|k|v, each [B,H,S,D], tf32-rounded
__device__ float g_o[(size_t)T_*HD_];         // [B,S,H,D] == [T, HD], tf32-rounded
__device__ float g_wqkvt[(size_t)3*HD_*E_];   // K-major [n][e], q|k|v, tf32-rounded
__device__ float g_wpt[(size_t)E_*HD_];       // K-major [n=e][c], tf32-rounded
__device__ float g_bqkv[3*HD_];               // concat bq|bk|bv

// ---------------------------------------------------------------------------
// PTX helpers (plain sm_103-target-safe: mma.sync + cp.async only)
// ---------------------------------------------------------------------------
__device__ __forceinline__ uint32_t smem_u32(const void* p) {
    return (uint32_t)__cvta_generic_to_shared(p);
}
__device__ __forceinline__ void cp_async16(uint32_t dst, const void* src) {
    asm volatile("cp.async.cg.shared.global [%0], [%1], 16;\n" :: "r"(dst), "l"(src));
}
__device__ __forceinline__ void cp_commit() {
    asm volatile("cp.async.commit_group;\n" ::: "memory");
}
template<int N> __device__ __forceinline__ void cp_wait() {
    asm volatile("cp.async.wait_group %0;\n" :: "n"(N) : "memory");
}
__device__ __forceinline__ uint32_t f2tf(float x) {
    uint32_t r;
    asm("cvt.rna.tf32.f32 %0, %1;" : "=r"(r) : "f"(x));
    return r;
}
__device__ __forceinline__ float f2tf_f(float x) {
    return __uint_as_float(f2tf(x));
}
__device__ __forceinline__ void mma_tf32(float* c,
    uint32_t a0, uint32_t a1, uint32_t a2, uint32_t a3,
    uint32_t b0, uint32_t b1)
{
    asm volatile(
        "mma.sync.aligned.m16n8k8.row.col.f32.tf32.tf32.f32 "
        "{%0,%1,%2,%3},{%4,%5,%6,%7},{%8,%9},{%0,%1,%2,%3};"
        : "+f"(c[0]), "+f"(c[1]), "+f"(c[2]), "+f"(c[3])
        : "r"(a0), "r"(a1), "r"(a2), "r"(a3), "r"(b0), "r"(b1));
}

// ---------------------------------------------------------------------------
// Weight transpose with tf32 pre-round: per-batch [R, C] -> [C, R]
// ---------------------------------------------------------------------------
__global__ void transpose_kernel(const float* __restrict__ src,
                                 float* __restrict__ dst, int R, int C)
{
    __shared__ float tile[32][33];
    const float* s = src + (size_t)blockIdx.z * R * C;
    float* d = dst + (size_t)blockIdx.z * R * C;
    int r0 = blockIdx.y * 32, c0 = blockIdx.x * 32;
    #pragma unroll
    for (int i = threadIdx.y; i < 32; i += 8)
        tile[i][threadIdx.x] = s[(size_t)(r0 + i) * C + c0 + threadIdx.x];
    __syncthreads();
    #pragma unroll
    for (int i = threadIdx.y; i < 32; i += 8)
        d[(size_t)(c0 + i) * R + r0 + threadIdx.x] = f2tf_f(tile[threadIdx.x][i]);
}

// tf32 pre-round copy (x)
__global__ void round_kernel(const float* __restrict__ src,
                             float* __restrict__ dst)
{
    int i = (blockIdx.x * 256 + threadIdx.x) * 4;
    float4 v = *(const float4*)(src + i);
    v.x = f2tf_f(v.x); v.y = f2tf_f(v.y);
    v.z = f2tf_f(v.z); v.w = f2tf_f(v.w);
    *(float4*)(dst + i) = v;
}

// concat biases
__global__ void bias_kernel(const float* __restrict__ bq,
                            const float* __restrict__ bk,
                            const float* __restrict__ bv,
                            float* __restrict__ dst)
{
    int i = blockIdx.x * 256 + threadIdx.x;  // 0..3071
    float v = (i < 1024) ? bq[i] : (i < 2048) ? bk[i - 1024] : bv[i - 2048];
    dst[i] = v;
}

// ---------------------------------------------------------------------------
// tf32 mma.sync GEMM: out = A[8192,K=1024] x Bw^T (+bias), Bw K-major [N,K]
// CTA 128x128, BK=32, 3-stage cp.async pipeline, 8 warps (4m x 2n),
// warp tile 32x64. Operands are pre-rounded tf32 (no runtime cvt).
// MODE 0: fused QKV, out routed by n-section into g_qkv (tf32-rounded store).
// MODE 1: out is final [T, E] fp32.
// ---------------------------------------------------------------------------
#define GEMM_BK     32
#define GEMM_STAGES 3
#define GEMM_KT     (E_ / GEMM_BK)            // 32
#define GEMM_LDS    36                        // floats per row (32 + 4 pad)
#define GEMM_TILE   (128 * GEMM_LDS)          // floats per tile
#define GEMM_STAGEF (2 * GEMM_TILE)           // floats per stage (A + B)
#define GEMM_SMEM   (GEMM_STAGES * GEMM_STAGEF * 4)   // 110592 B

__device__ __forceinline__ void gemm_load_stage(
    const float* __restrict__ Ag, const float* __restrict__ Bg,
    uint32_t abase, uint32_t bbase, int tid)
{
    #pragma unroll
    for (int j = 0; j < 4; j++) {
        int p = tid + j * 256;
        int r = p >> 3;                 // 0..127
        int ch = p & 7;                 // 0..7
        uint32_t off = (uint32_t)(r * (GEMM_LDS * 4) + ch * 16);
        cp_async16(abase + off, (const char*)Ag + (size_t)r * (E_ * 4) + ch * 16);
        cp_async16(bbase + off, (const char*)Bg + (size_t)r * (E_ * 4) + ch * 16);
    }
}

template<int MODE>
__global__ __launch_bounds__(256, 2) void gemm_mma(
    const float* __restrict__ A,     // [8192, 1024] K-contiguous (pre-rounded)
    const float* __restrict__ Bw,    // [N, 1024] K-contiguous (pre-rounded)
    const float* __restrict__ bias,  // [N]
    float* __restrict__ out)
{
    extern __shared__ __align__(16) float smem[];
    uint32_t sb = smem_u32(smem);

    int tid = threadIdx.x;
    int wid = tid >> 5, lane = tid & 31;
    int g = lane >> 2, c = lane & 3;
    int wm = wid & 3, wn = wid >> 2;          // 4 x 2 warp grid
    int m0 = blockIdx.x * 128;
    int n0 = blockIdx.y * 128;

    const float* Abase = A + (size_t)m0 * E_;
    const float* Bbase = Bw + (size_t)n0 * E_;

    float cfr[2][8][4];
    #pragma unroll
    for (int mf = 0; mf < 2; mf++)
        #pragma unroll
        for (int nf = 0; nf < 8; nf++)
            #pragma unroll
            for (int i = 0; i < 4; i++) cfr[mf][nf][i] = 0.f;

    // Prologue: fill first 2 stages
    #pragma unroll
    for (int s = 0; s < GEMM_STAGES - 1; s++) {
        gemm_load_stage(Abase + s * GEMM_BK, Bbase + s * GEMM_BK,
                        sb + s * GEMM_STAGEF * 4,
                        sb + (s * GEMM_STAGEF + GEMM_TILE) * 4, tid);
        cp_commit();
    }

    for (int kt = 0; kt < GEMM_KT; kt++) {
        cp_wait<GEMM_STAGES - 2>();
        __syncthreads();

        int s = kt % GEMM_STAGES;
        const float* As = smem + s * GEMM_STAGEF;
        const float* Bs = As + GEMM_TILE;

        #pragma unroll
        for (int ks = 0; ks < 4; ks++) {
            int k0 = ks * 8;
            uint32_t a[2][4];
            #pragma unroll
            for (int mf = 0; mf < 2; mf++) {
                int r = wm * 32 + mf * 16 + g;
                a[mf][0] = __float_as_uint(As[r * GEMM_LDS + k0 + c]);
                a[mf][1] = __float_as_uint(As[(r + 8) * GEMM_LDS + k0 + c]);
                a[mf][2] = __float_as_uint(As[r * GEMM_LDS + k0 + c + 4]);
                a[mf][3] = __float_as_uint(As[(r + 8) * GEMM_LDS + k0 + c + 4]);
            }
            #pragma unroll
            for (int nf = 0; nf < 8; nf++) {
                int n = wn * 64 + nf * 8 + g;
                uint32_t b0 = __float_as_uint(Bs[n * GEMM_LDS + k0 + c]);
                uint32_t b1 = __float_as_uint(Bs[n * GEMM_LDS + k0 + c + 4]);
                mma_tf32(cfr[0][nf], a[0][0], a[0][1], a[0][2], a[0][3], b0, b1);
                mma_tf32(cfr[1][nf], a[1][0], a[1][1], a[1][2], a[1][3], b0, b1);
            }
        }

        int ktn = kt + GEMM_STAGES - 1;
        if (ktn < GEMM_KT) {
            int sn = ktn % GEMM_STAGES;
            gemm_load_stage(Abase + ktn * GEMM_BK, Bbase + ktn * GEMM_BK,
                            sb + sn * GEMM_STAGEF * 4,
                            sb + (sn * GEMM_STAGEF + GEMM_TILE) * 4, tid);
        }
        cp_commit();
    }

    // Epilogue
    float* ob = out;
    if (MODE == 0) ob = out + (size_t)(n0 >> 10) * ((size_t)T_ * HD_);
    #pragma unroll
    for (int mf = 0; mf < 2; mf++) {
        #pragma unroll
        for (int half = 0; half < 2; half++) {
            int row = wm * 32 + mf * 16 + g + half * 8;
            int t = m0 + row;
            #pragma unroll
            for (int nf = 0; nf < 8; nf++) {
                int col = n0 + wn * 64 + nf * 8 + 2 * c;
                float2 v;
                v.x = cfr[mf][nf][2 * half + 0] + bias[col];
                v.y = cfr[mf][nf][2 * half + 1] + bias[col + 1];
                if (MODE == 0) {
                    v.x = f2tf_f(v.x);   // consumed by tf32 attention MMAs
                    v.y = f2tf_f(v.y);
                    int cs = col & 1023;
                    int b = t >> 11, s_ = t & 2047;
                    int h = cs >> 6, d0 = cs & 63;
                    *(float2*)(ob + (((size_t)(b * H_ + h)) * S_ + s_) * D_ + d0) = v;
                } else {
                    *(float2*)(ob + (size_t)t * E_ + col) = v;
                }
            }
        }
    }
}

// ---------------------------------------------------------------------------
// Flash attention (tf32 mma.sync, causal). BQ=128, BKV=64, 512 threads.
// K/V loaded untransposed via double-buffered cp.async.
// 16 warps = 4m x 4n grid, warp tile 32m x 16n. Operands pre-rounded tf32.
// Output [B,S,H,D], tf32-rounded (feeds proj GEMM).
// ---------------------------------------------------------------------------
#define AT_STR 68
// floats: Qs 128*68 + Ks 2*64*68 + Vs 2*64*68 + Ss 128*68 + 3*128
#define ATTN_SMEM ((128*AT_STR + 2*64*AT_STR + 2*64*AT_STR + 128*AT_STR + 3*128) * 4)

__global__ __launch_bounds__(512, 1) void attn_kernel(
    const float* __restrict__ q,
    const float* __restrict__ k,
    const float* __restrict__ v,
    float* __restrict__ o)
{
    extern __shared__ float sm[];
    float* Qs = sm;                          // [128][68]
    float* Ks = Qs + 128 * AT_STR;           // [2][64][68]
    float* Vs = Ks + 2 * 64 * AT_STR;        // [2][64][68]
    float* Ss = Vs + 2 * 64 * AT_STR;        // [128][68]
    float* mrow = Ss + 128 * AT_STR;
    float* lrow = mrow + 128;
    float* arow = lrow + 128;

    uint32_t sb = smem_u32(sm);
    uint32_t Qs_u = sb;
    uint32_t Ks_u = Qs_u + 128 * AT_STR * 4;
    uint32_t Vs_u = Ks_u + 2 * 64 * AT_STR * 4;

    int tid = threadIdx.x;
    int lane = tid & 31, wid = tid >> 5;
    int g = lane >> 2, c = lane & 3;
    int wm = wid & 3, wn = wid >> 2;         // 4 x 4 warp grid
    int q0 = ((int)gridDim.x - 1 - (int)blockIdx.x) * 128;   // longest first
    int bh = blockIdx.y;

    const float* qb = q + (size_t)bh * S_ * D_;
    const float* kb = k + (size_t)bh * S_ * D_;
    const float* vb = v + (size_t)bh * S_ * D_;

    // Load Q (group 0) + first K/V stage (group 0)
    #pragma unroll
    for (int it = 0; it < 4; it++) {
        int p = tid + it * 512;              // 0..2047
        int r = p >> 4;                      // 0..127
        int ch = p & 15;                     // 0..15
        cp_async16(Qs_u + (uint32_t)(r * AT_STR + ch * 4) * 4,
                   qb + (size_t)(q0 + r) * D_ + ch * 4);
    }
    #pragma unroll
    for (int it = 0; it < 4; it++) {
        int p = tid + it * 512;              // 0..2047
        int sel = p >> 10;                   // 0=K, 1=V
        int pp = p & 1023;
        int r = pp >> 4, ch = pp & 15;
        uint32_t dst = (sel ? Vs_u : Ks_u) + (uint32_t)(r * AT_STR + ch * 4) * 4;
        const float* src = (sel ? vb : kb) + (size_t)r * D_ + ch * 4;
        cp_async16(dst, src);
    }
    cp_commit();

    if (tid < 128) { mrow[tid] = -1e30f; lrow[tid] = 0.f; }

    float ofr[2][2][4];
    #pragma unroll
    for (int mf = 0; mf < 2; mf++)
        #pragma unroll
        for (int nf = 0; nf < 2; nf++)
            #pragma unroll
            for (int i = 0; i < 4; i++) ofr[mf][nf][i] = 0.f;

    int ntiles = q0 / 64 + 2;

    for (int it = 0; it < ntiles; it++) {
        int j0 = it * 64;
        int st = it & 1;

        // Prefetch next K/V stage
        if (it + 1 < ntiles) {
            int j0n = j0 + 64;
            uint32_t kd = Ks_u + (uint32_t)((st ^ 1) * 64 * AT_STR) * 4;
            uint32_t vd = Vs_u + (uint32_t)((st ^ 1) * 64 * AT_STR) * 4;
            #pragma unroll
            for (int l = 0; l < 4; l++) {
                int p = tid + l * 512;
                int sel = p >> 10;
                int pp = p & 1023;
                int r = pp >> 4, ch = pp & 15;
                uint32_t dst = (sel ? vd : kd) + (uint32_t)(r * AT_STR + ch * 4) * 4;
                const float* src = (sel ? vb : kb) + (size_t)(j0n + r) * D_ + ch * 4;
                cp_async16(dst, src);
            }
        }
        cp_commit();
        cp_wait<1>();
        __syncthreads();

        const float* Kt = Ks + st * 64 * AT_STR;
        const float* Vt = Vs + st * 64 * AT_STR;

        // S = Q @ K^T  (m128 n64 k64)
        float sfr[2][2][4];
        #pragma unroll
        for (int mf = 0; mf < 2; mf++)
            #pragma unroll
            for (int nf = 0; nf < 2; nf++)
                #pragma unroll
                for (int i = 0; i < 4; i++) sfr[mf][nf][i] = 0.f;

        #pragma unroll
        for (int kk = 0; kk < 8; kk++) {
            int k0 = kk * 8;
            uint32_t a[2][4];
            #pragma unroll
            for (int mf = 0; mf < 2; mf++) {
                int r = wm * 32 + mf * 16 + g;
                a[mf][0] = __float_as_uint(Qs[r * AT_STR + k0 + c]);
                a[mf][1] = __float_as_uint(Qs[(r + 8) * AT_STR + k0 + c]);
                a[mf][2] = __float_as_uint(Qs[r * AT_STR + k0 + c + 4]);
                a[mf][3] = __float_as_uint(Qs[(r + 8) * AT_STR + k0 + c + 4]);
            }
            #pragma unroll
            for (int nf = 0; nf < 2; nf++) {
                int n = wn * 16 + nf * 8 + g;
                uint32_t b0 = __float_as_uint(Kt[n * AT_STR + k0 + c]);
                uint32_t b1 = __float_as_uint(Kt[n * AT_STR + k0 + c + 4]);
                mma_tf32(sfr[0][nf], a[0][0], a[0][1], a[0][2], a[0][3], b0, b1);
                mma_tf32(sfr[1][nf], a[1][0], a[1][1], a[1][2], a[1][3], b0, b1);
            }
        }

        // Scale + causal mask + store scores to smem
        bool needmask = (j0 + 64 > q0);
        #pragma unroll
        for (int mf = 0; mf < 2; mf++) {
            #pragma unroll
            for (int nf = 0; nf < 2; nf++) {
                int col = wn * 16 + nf * 8 + 2 * c;
                #pragma unroll
                for (int half = 0; half < 2; half++) {
                    int row = wm * 32 + mf * 16 + g + half * 8;
                    int gi = q0 + row;
                    float v0 = sfr[mf][nf][2 * half + 0] * 0.125f;
                    float v1 = sfr[mf][nf][2 * half + 1] * 0.125f;
                    if (needmask) {
                        if (j0 + col > gi) v0 = -1e30f;
                        if (j0 + col + 1 > gi) v1 = -1e30f;
                    }
                    float2 sv; sv.x = v0; sv.y = v1;
                    *(float2*)&Ss[row * AT_STR + col] = sv;
                }
            }
        }
        __syncthreads();

        // Online softmax: warp per row (16 warps x 8 rows). P rounded to tf32.
        #pragma unroll
        for (int rr = 0; rr < 8; rr++) {
            int row = wid * 8 + rr;
            float v0 = Ss[row * AT_STR + lane];
            float v1 = Ss[row * AT_STR + 32 + lane];
            float mx = fmaxf(v0, v1);
            #pragma unroll
            for (int off = 16; off > 0; off >>= 1)
                mx = fmaxf(mx, __shfl_xor_sync(0xffffffffu, mx, off));
            float mold = mrow[row];
            float mnew = fmaxf(mold, mx);
            float p0 = f2tf_f(__expf(v0 - mnew));
            float p1 = f2tf_f(__expf(v1 - mnew));
            Ss[row * AT_STR + lane] = p0;
            Ss[row * AT_STR + 32 + lane] = p1;
            float sum = p0 + p1;
            #pragma unroll
            for (int off = 16; off > 0; off >>= 1)
                sum += __shfl_xor_sync(0xffffffffu, sum, off);
            if (lane == 0) {
                float alpha = __expf(mold - mnew);
                arow[row] = alpha;
                lrow[row] = lrow[row] * alpha + sum;
                mrow[row] = mnew;
            }
        }
        __syncthreads();

        // O = O*alpha + P @ V
        #pragma unroll
        for (int mf = 0; mf < 2; mf++) {
            int r = wm * 32 + mf * 16 + g;
            float al0 = arow[r];
            float al1 = arow[r + 8];
            #pragma unroll
            for (int nf = 0; nf < 2; nf++) {
                ofr[mf][nf][0] *= al0;
                ofr[mf][nf][1] *= al0;
                ofr[mf][nf][2] *= al1;
                ofr[mf][nf][3] *= al1;
            }
        }

        #pragma unroll
        for (int kk = 0; kk < 8; kk++) {
            int k0 = kk * 8;
            uint32_t a[2][4];
            #pragma unroll
            for (int mf = 0; mf < 2; mf++) {
                int r = wm * 32 + mf * 16 + g;
                a[mf][0] = __float_as_uint(Ss[r * AT_STR + k0 + c]);
                a[mf][1] = __float_as_uint(Ss[(r + 8) * AT_STR + k0 + c]);
                a[mf][2] = __float_as_uint(Ss[r * AT_STR + k0 + c + 4]);
                a[mf][3] = __float_as_uint(Ss[(r + 8) * AT_STR + k0 + c + 4]);
            }
            #pragma unroll
            for (int nf = 0; nf < 2; nf++) {
                int n = wn * 16 + nf * 8 + g;
                uint32_t b0 = __float_as_uint(Vt[(k0 + c) * AT_STR + n]);
                uint32_t b1 = __float_as_uint(Vt[(k0 + c + 4) * AT_STR + n]);
                mma_tf32(ofr[0][nf], a[0][0], a[0][1], a[0][2], a[0][3], b0, b1);
                mma_tf32(ofr[1][nf], a[1][0], a[1][1], a[1][2], a[1][3], b0, b1);
            }
        }
        __syncthreads();   // protect Ss/Vs/Ks before next iteration writes
    }

    // Finalize: divide by l, round to tf32, write out [B,S,H,D]
    int b = bh >> 4, h = bh & 15;
    #pragma unroll
    for (int mf = 0; mf < 2; mf++) {
        #pragma unroll
        for (int half = 0; half < 2; half++) {
            int row = wm * 32 + mf * 16 + g + half * 8;
            float inv = 1.f / lrow[row];
            size_t base = (((size_t)b * S_ + (q0 + row)) * H_ + h) * D_;
            #pragma unroll
            for (int nf = 0; nf < 2; nf++) {
                int col = wn * 16 + nf * 8 + 2 * c;
                float2 res;
                res.x = f2tf_f(ofr[mf][nf][2 * half + 0] * inv);
                res.y = f2tf_f(ofr[mf][nf][2 * half + 1] * inv);
                *(float2*)(o + base + col) = res;
            }
        }
    }
}

// ---------------------------------------------------------------------------
extern "C" void kernel_launch(void* const* d_in, const int* in_sizes, int n_in,
                              void* d_out, int out_size)
{
    const float* x  = (const float*)d_in[0];
    const float* Wq = (const float*)d_in[1];
    const float* bq = (const float*)d_in[2];
    const float* Wk = (const float*)d_in[3];
    const float* bk = (const float*)d_in[4];
    const float* Wv = (const float*)d_in[5];
    const float* bv = (const float*)d_in[6];
    const float* Wp = (const float*)d_in[7];
    const float* bp = (const float*)d_in[8];
    float* out = (float*)d_out;

    float *xp, *qkvp, *op, *wqkvt, *wpt, *bqkv;
    cudaGetSymbolAddress((void**)&xp, g_x);
    cudaGetSymbolAddress((void**)&qkvp, g_qkv);
    cudaGetSymbolAddress((void**)&op, g_o);
    cudaGetSymbolAddress((void**)&wqkvt, g_wqkvt);
    cudaGetSymbolAddress((void**)&wpt, g_wpt);
    cudaGetSymbolAddress((void**)&bqkv, g_bqkv);

    cudaFuncSetAttribute(attn_kernel,
                         cudaFuncAttributeMaxDynamicSharedMemorySize, ATTN_SMEM);
    cudaFuncSetAttribute(gemm_mma<0>,
                         cudaFuncAttributeMaxDynamicSharedMemorySize, GEMM_SMEM);
    cudaFuncSetAttribute(gemm_mma<1>,
                         cudaFuncAttributeMaxDynamicSharedMemorySize, GEMM_SMEM);

    // Pre-round x, transpose+round weights, concat biases
    round_kernel<<<T_ * E_ / 1024, 256>>>(x, xp);
    dim3 tb(32, 8);
    dim3 tgw(D_ / 32, E_ / 32, H_);                  // W[h]: [E,D] -> [D,E]
    transpose_kernel<<<tgw, tb>>>(Wq, wqkvt, E_, D_);
    transpose_kernel<<<tgw, tb>>>(Wk, wqkvt + (size_t)HD_ * E_, E_, D_);
    transpose_kernel<<<tgw, tb>>>(Wv, wqkvt + (size_t)2 * HD_ * E_, E_, D_);
    dim3 tgp(E_ / 32, HD_ / 32, 1);                  // Wp: [HD,E] -> [E,HD]
    transpose_kernel<<<tgp, tb>>>(Wp, wpt, HD_, E_);
    bias_kernel<<<12, 256>>>(bq, bk, bv, bqkv);

    // Fused QKV projection (tf32 mma.sync), N = 3072
    dim3 gg(T_ / 128, 3 * HD_ / 128);                // 64 x 24
    gemm_mma<0><<<gg, 256, GEMM_SMEM>>>(xp, wqkvt, bqkv, qkvp);

    // Attention
    float* qp = qkvp;
    float* kp = qkvp + (size_t)T_ * HD_;
    float* vp = qkvp + (size_t)2 * T_ * HD_;
    dim3 gattn(S_ / 128, B_ * H_);                   // 16 x 64
    attn_kernel<<<gattn, 512, ATTN_SMEM>>>(qp, kp, vp, op);

    // Output projection
    dim3 gp(T_ / 128, E_ / 128);                     // 64 x 8
    gemm_mma<1><<<gp, 256, GEMM_SMEM>>>(op, wpt, bp, out);
}

// round 5
// speedup vs baseline: 3.8920x; 1.4422x over previous
#include <cuda_runtime.h>
#include <cuda_fp16.h>
#include <cstdint>
#include <math.h>

#define B_  4
#define S_  2048
#define E_  1024
#define H_  16
#define D_  64
#define T_  (B_*S_)     // 8192 tokens
#define HD_ (H_*D_)     // 1024

// ---------------------------------------------------------------------------
// Scratch (static device arrays; no runtime allocation)
// ---------------------------------------------------------------------------
__device__ __half g_x[(size_t)T_*E_];          // fp16 x [T,E]
__device__ __half g_qkv[(size_t)3*T_*HD_];     // q[B,H,S,D] | k[B,H,S,D] | v[B,H,D,S]
__device__ __half g_o[(size_t)T_*HD_];         // ctx [B,S,H,D] == [T, HD]
__device__ __half g_wqkvt[(size_t)3*HD_*E_];   // K-major [n][e], q|k|v
__device__ __half g_wpt[(size_t)E_*HD_];       // K-major [n=e][c]
__device__ float  g_bqkv[3*HD_];               // concat bq|bk|bv (fp32)

// ---------------------------------------------------------------------------
// PTX helpers (plain sm_103-target-safe: mma.sync + cp.async only)
// ---------------------------------------------------------------------------
__device__ __forceinline__ uint32_t smem_u32(const void* p) {
    return (uint32_t)__cvta_generic_to_shared(p);
}
__device__ __forceinline__ void cp_async16(uint32_t dst, const void* src) {
    asm volatile("cp.async.cg.shared.global [%0], [%1], 16;\n" :: "r"(dst), "l"(src));
}
__device__ __forceinline__ void cp_commit() {
    asm volatile("cp.async.commit_group;\n" ::: "memory");
}
template<int N> __device__ __forceinline__ void cp_wait() {
    asm volatile("cp.async.wait_group %0;\n" :: "n"(N) : "memory");
}
__device__ __forceinline__ void mma_f16(float* c,
    uint32_t a0, uint32_t a1, uint32_t a2, uint32_t a3,
    uint32_t b0, uint32_t b1)
{
    asm volatile(
        "mma.sync.aligned.m16n8k16.row.col.f32.f16.f16.f32 "
        "{%0,%1,%2,%3},{%4,%5,%6,%7},{%8,%9},{%0,%1,%2,%3};"
        : "+f"(c[0]), "+f"(c[1]), "+f"(c[2]), "+f"(c[3])
        : "r"(a0), "r"(a1), "r"(a2), "r"(a3), "r"(b0), "r"(b1));
}
__device__ __forceinline__ uint32_t ldh2(const __half* p) {
    return *(const uint32_t*)p;
}

// ---------------------------------------------------------------------------
// Pre-pass kernels
// ---------------------------------------------------------------------------
// x fp32 -> fp16 (8 elems / thread)
__global__ void round_kernel(const float* __restrict__ src,
                             __half* __restrict__ dst)
{
    int i = (blockIdx.x * 256 + threadIdx.x) * 8;
    float4 v0 = *(const float4*)(src + i);
    float4 v1 = *(const float4*)(src + i + 4);
    __half2 h0 = __floats2half2_rn(v0.x, v0.y);
    __half2 h1 = __floats2half2_rn(v0.z, v0.w);
    __half2 h2 = __floats2half2_rn(v1.x, v1.y);
    __half2 h3 = __floats2half2_rn(v1.z, v1.w);
    uint4 st;
    st.x = *(uint32_t*)&h0; st.y = *(uint32_t*)&h1;
    st.z = *(uint32_t*)&h2; st.w = *(uint32_t*)&h3;
    *(uint4*)(dst + i) = st;
}

// QKV weights: W[h] [E,64] fp32 -> [64,E] fp16, all 3*H slabs in one launch
__global__ void transpose_qkv_kernel(const float* __restrict__ Wq,
                                     const float* __restrict__ Wk,
                                     const float* __restrict__ Wv,
                                     __half* __restrict__ dst)
{
    __shared__ float tile[32][33];
    int z = blockIdx.z;                 // 0..47 = sec*16 + h
    const float* W = (z < 16) ? Wq : (z < 32) ? Wk : Wv;
    const float* s = W + (size_t)(z & 15) * E_ * D_;
    __half* d = dst + (size_t)z * D_ * E_;
    int r0 = blockIdx.y * 32, c0 = blockIdx.x * 32;   // r: E dim, c: D dim
    #pragma unroll
    for (int i = threadIdx.y; i < 32; i += 8)
        tile[i][threadIdx.x] = s[(size_t)(r0 + i) * D_ + c0 + threadIdx.x];
    __syncthreads();
    #pragma unroll
    for (int i = threadIdx.y; i < 32; i += 8)
        d[(size_t)(c0 + i) * E_ + r0 + threadIdx.x] =
            __float2half(tile[threadIdx.x][i]);
}

// Wp [HD,E] fp32 -> [E,HD] fp16
__global__ void transpose_wp_kernel(const float* __restrict__ src,
                                    __half* __restrict__ dst)
{
    __shared__ float tile[32][33];
    int r0 = blockIdx.y * 32, c0 = blockIdx.x * 32;
    #pragma unroll
    for (int i = threadIdx.y; i < 32; i += 8)
        tile[i][threadIdx.x] = src[(size_t)(r0 + i) * E_ + c0 + threadIdx.x];
    __syncthreads();
    #pragma unroll
    for (int i = threadIdx.y; i < 32; i += 8)
        dst[(size_t)(c0 + i) * HD_ + r0 + threadIdx.x] =
            __float2half(tile[threadIdx.x][i]);
}

__global__ void bias_kernel(const float* __restrict__ bq,
                            const float* __restrict__ bk,
                            const float* __restrict__ bv,
                            float* __restrict__ dst)
{
    int i = blockIdx.x * 256 + threadIdx.x;  // 0..3071
    float v = (i < 1024) ? bq[i] : (i < 2048) ? bk[i - 1024] : bv[i - 2048];
    dst[i] = v;
}

// ---------------------------------------------------------------------------
// fp16 mma.sync GEMM: out = A[8192,K=1024] x Bw^T (+bias), Bw K-major [N,K]
// CTA 128x128, BK=32 halfs, 4-stage cp.async pipeline, 8 warps (4m x 2n),
// warp tile 32x64, m16n8k16 fragments, fp32 accumulate.
// MODE 0: fused QKV -> g_qkv (half; q/k as [B,H,S,D], v as [B,H,D,S]).
// MODE 1: final [T, E] fp32.
// ---------------------------------------------------------------------------
#define GEMM_BK     32                       // halfs per k-tile
#define GEMM_STAGES 4
#define GEMM_KT     (E_ / GEMM_BK)           // 32
#define GEMM_STR    40                       // halfs per smem row (32+8 pad)
#define GEMM_TILEH  (128 * GEMM_STR)         // halfs per tile
#define GEMM_STAGEH (2 * GEMM_TILEH)
#define GEMM_SMEM   (GEMM_STAGES * GEMM_STAGEH * 2)    // 81920 B

__device__ __forceinline__ void gemm_load_stage(
    const __half* __restrict__ Ag, const __half* __restrict__ Bg,
    uint32_t abase, uint32_t bbase, int tid)
{
    #pragma unroll
    for (int j = 0; j < 2; j++) {
        int p = tid + j * 256;
        int r = p >> 1;                 // 0..127... wait (see below)
        int ch = p & 1;
        // 128 rows x 4 chunks(16B) per tile = 512 chunks; 256 thr -> 2 iters
        r = p >> 2;                     // 0..127
        ch = p & 3;                     // 0..3
        uint32_t off = (uint32_t)(r * (GEMM_STR * 2) + ch * 16);
        cp_async16(abase + off, Ag + (size_t)r * E_ + ch * 8);
        cp_async16(bbase + off, Bg + (size_t)r * E_ + ch * 8);
    }
}

template<int MODE>
__global__ __launch_bounds__(256, 2) void gemm_mma(
    const __half* __restrict__ A,     // [8192, 1024] K-contiguous
    const __half* __restrict__ Bw,    // [N, 1024] K-contiguous
    const float* __restrict__ bias,   // [N]
    void* __restrict__ outp)
{
    extern __shared__ __align__(16) __half smem[];
    uint32_t sb = smem_u32(smem);

    int tid = threadIdx.x;
    int wid = tid >> 5, lane = tid & 31;
    int g = lane >> 2, c = lane & 3;
    int wm = wid & 3, wn = wid >> 2;          // 4 x 2 warp grid
    int m0 = blockIdx.x * 128;
    int n0 = blockIdx.y * 128;

    const __half* Abase = A + (size_t)m0 * E_;
    const __half* Bbase = Bw + (size_t)n0 * E_;

    float cfr[2][8][4];
    #pragma unroll
    for (int mf = 0; mf < 2; mf++)
        #pragma unroll
        for (int nf = 0; nf < 8; nf++)
            #pragma unroll
            for (int i = 0; i < 4; i++) cfr[mf][nf][i] = 0.f;

    #pragma unroll
    for (int s = 0; s < GEMM_STAGES - 1; s++) {
        gemm_load_stage(Abase + s * GEMM_BK, Bbase + s * GEMM_BK,
                        sb + s * GEMM_STAGEH * 2,
                        sb + (s * GEMM_STAGEH + GEMM_TILEH) * 2, tid);
        cp_commit();
    }

    for (int kt = 0; kt < GEMM_KT; kt++) {
        cp_wait<GEMM_STAGES - 2>();
        __syncthreads();

        int s = kt & (GEMM_STAGES - 1);
        const __half* As = smem + s * GEMM_STAGEH;
        const __half* Bs = As + GEMM_TILEH;

        #pragma unroll
        for (int kc = 0; kc < 2; kc++) {
            int k0 = kc * 16;
            uint32_t a[2][4];
            #pragma unroll
            for (int mf = 0; mf < 2; mf++) {
                int r = wm * 32 + mf * 16 + g;
                a[mf][0] = ldh2(&As[r * GEMM_STR + k0 + 2 * c]);
                a[mf][1] = ldh2(&As[(r + 8) * GEMM_STR + k0 + 2 * c]);
                a[mf][2] = ldh2(&As[r * GEMM_STR + k0 + 2 * c + 8]);
                a[mf][3] = ldh2(&As[(r + 8) * GEMM_STR + k0 + 2 * c + 8]);
            }
            #pragma unroll
            for (int nf = 0; nf < 8; nf++) {
                int n = wn * 64 + nf * 8 + g;
                uint32_t b0 = ldh2(&Bs[n * GEMM_STR + k0 + 2 * c]);
                uint32_t b1 = ldh2(&Bs[n * GEMM_STR + k0 + 2 * c + 8]);
                mma_f16(cfr[0][nf], a[0][0], a[0][1], a[0][2], a[0][3], b0, b1);
                mma_f16(cfr[1][nf], a[1][0], a[1][1], a[1][2], a[1][3], b0, b1);
            }
        }

        int ktn = kt + GEMM_STAGES - 1;
        if (ktn < GEMM_KT) {
            int sn = ktn & (GEMM_STAGES - 1);
            gemm_load_stage(Abase + ktn * GEMM_BK, Bbase + ktn * GEMM_BK,
                            sb + sn * GEMM_STAGEH * 2,
                            sb + (sn * GEMM_STAGEH + GEMM_TILEH) * 2, tid);
        }
        cp_commit();
    }

    // Epilogue
    #pragma unroll
    for (int mf = 0; mf < 2; mf++) {
        #pragma unroll
        for (int half_ = 0; half_ < 2; half_++) {
            int row = wm * 32 + mf * 16 + g + half_ * 8;
            int t = m0 + row;
            #pragma unroll
            for (int nf = 0; nf < 8; nf++) {
                int col = n0 + wn * 64 + nf * 8 + 2 * c;
                float vx = cfr[mf][nf][2 * half_ + 0] + bias[col];
                float vy = cfr[mf][nf][2 * half_ + 1] + bias[col + 1];
                if (MODE == 0) {
                    __half* ob = (__half*)outp + (size_t)(col >> 10) * ((size_t)T_ * HD_);
                    int cs = col & 1023;
                    int b = t >> 11, s_ = t & 2047;
                    int h = cs >> 6, d0 = cs & 63;
                    if (col < 2048) {
                        // q, k: [B,H,S,D]
                        __half2 hv = __floats2half2_rn(vx, vy);
                        *(__half2*)(ob + (((size_t)(b * H_ + h)) * S_ + s_) * D_ + d0) = hv;
                    } else {
                        // v: [B,H,D,S] (transposed for PV mma)
                        ob[(((size_t)(b * H_ + h)) * D_ + d0) * S_ + s_] = __float2half(vx);
                        ob[(((size_t)(b * H_ + h)) * D_ + d0 + 1) * S_ + s_] = __float2half(vy);
                    }
                } else {
                    float2 v; v.x = vx; v.y = vy;
                    *(float2*)((float*)outp + (size_t)t * E_ + col) = v;
                }
            }
        }
    }
}

// ---------------------------------------------------------------------------
// Flash attention (fp16 mma.sync, causal). BQ=128, BKV=64, 512 threads.
// K [B,H,S,D], V [B,H,D,S] (pre-transposed), double-buffered cp.async.
// 16 warps = 4m x 4n, warp tile 32m x 16n. fp32 softmax, P stored half.
// Output ctx [B,S,H,D] half.
// ---------------------------------------------------------------------------
#define AT_STRH 72          // halfs (64 + 8 pad)
#define AT_STRS 68          // floats for scores
// bytes: Qs 128*72*2 + Ks 2*64*72*2 + Vs 2*64*72*2 + Ss 128*68*4 + Ps 128*72*2 + 3*128*4
#define ATTN_SMEM (128*AT_STRH*2 + 2*64*AT_STRH*2 + 2*64*AT_STRH*2 \
                   + 128*AT_STRS*4 + 128*AT_STRH*2 + 3*128*4)

__global__ __launch_bounds__(512, 1) void attn_kernel(
    const __half* __restrict__ q,
    const __half* __restrict__ k,
    const __half* __restrict__ v,     // [B,H,D,S]
    __half* __restrict__ o)
{
    extern __shared__ __align__(16) char smraw[];
    __half* Qs = (__half*)smraw;                        // [128][72]
    __half* Ks = Qs + 128 * AT_STRH;                    // [2][64][72]
    __half* Vs = Ks + 2 * 64 * AT_STRH;                 // [2][64][72] (rows=d)
    float*  Ss = (float*)(Vs + 2 * 64 * AT_STRH);       // [128][68]
    __half* Ps = (__half*)(Ss + 128 * AT_STRS);         // [128][72]
    float* mrow = (float*)(Ps + 128 * AT_STRH);
    float* lrow = mrow + 128;
    float* arow = lrow + 128;

    uint32_t Qs_u = smem_u32(Qs);
    uint32_t Ks_u = smem_u32(Ks);
    uint32_t Vs_u = smem_u32(Vs);

    int tid = threadIdx.x;
    int lane = tid & 31, wid = tid >> 5;
    int g = lane >> 2, c = lane & 3;
    int wm = wid & 3, wn = wid >> 2;         // 4 x 4 warp grid
    int q0 = ((int)gridDim.x - 1 - (int)blockIdx.x) * 128;   // longest first
    int bh = blockIdx.y;

    const __half* qb = q + (size_t)bh * S_ * D_;
    const __half* kb = k + (size_t)bh * S_ * D_;
    const __half* vb = v + (size_t)bh * D_ * S_;

    // Q: 128 rows x 8 chunks(16B) = 1024; 512 thr -> 2 iters
    #pragma unroll
    for (int it = 0; it < 2; it++) {
        int p = tid + it * 512;
        int r = p >> 3, ch = p & 7;
        cp_async16(Qs_u + (uint32_t)(r * AT_STRH + ch * 8) * 2,
                   qb + (size_t)(q0 + r) * D_ + ch * 8);
    }
    // K stage0 (rows=j) + V stage0 (rows=d): 512 + 512 chunks
    #pragma unroll
    for (int it = 0; it < 2; it++) {
        int p = tid + it * 512;
        int sel = p >> 9;                    // 0=K, 1=V
        int pp = p & 511;
        int r = pp >> 3, ch = pp & 7;
        if (sel == 0)
            cp_async16(Ks_u + (uint32_t)(r * AT_STRH + ch * 8) * 2,
                       kb + (size_t)r * D_ + ch * 8);
        else
            cp_async16(Vs_u + (uint32_t)(r * AT_STRH + ch * 8) * 2,
                       vb + (size_t)r * S_ + ch * 8);
    }
    cp_commit();

    if (tid < 128) { mrow[tid] = -1e30f; lrow[tid] = 0.f; }

    float ofr[2][2][4];
    #pragma unroll
    for (int mf = 0; mf < 2; mf++)
        #pragma unroll
        for (int nf = 0; nf < 2; nf++)
            #pragma unroll
            for (int i = 0; i < 4; i++) ofr[mf][nf][i] = 0.f;

    int ntiles = q0 / 64 + 2;

    for (int it = 0; it < ntiles; it++) {
        int j0 = it * 64;
        int st = it & 1;

        // Prefetch next K/V stage
        if (it + 1 < ntiles) {
            int j0n = j0 + 64;
            uint32_t kd = Ks_u + (uint32_t)((st ^ 1) * 64 * AT_STRH) * 2;
            uint32_t vd = Vs_u + (uint32_t)((st ^ 1) * 64 * AT_STRH) * 2;
            #pragma unroll
            for (int l = 0; l < 2; l++) {
                int p = tid + l * 512;
                int sel = p >> 9;
                int pp = p & 511;
                int r = pp >> 3, ch = pp & 7;
                if (sel == 0)
                    cp_async16(kd + (uint32_t)(r * AT_STRH + ch * 8) * 2,
                               kb + (size_t)(j0n + r) * D_ + ch * 8);
                else
                    cp_async16(vd + (uint32_t)(r * AT_STRH + ch * 8) * 2,
                               vb + (size_t)r * S_ + j0n + ch * 8);
            }
        }
        cp_commit();
        cp_wait<1>();
        __syncthreads();

        const __half* Kt = Ks + st * 64 * AT_STRH;
        const __half* Vt = Vs + st * 64 * AT_STRH;

        // S = Q @ K^T  (m128 n64 k64): 4 k16 chunks
        float sfr[2][2][4];
        #pragma unroll
        for (int mf = 0; mf < 2; mf++)
            #pragma unroll
            for (int nf = 0; nf < 2; nf++)
                #pragma unroll
                for (int i = 0; i < 4; i++) sfr[mf][nf][i] = 0.f;

        #pragma unroll
        for (int kc = 0; kc < 4; kc++) {
            int k0 = kc * 16;
            uint32_t a[2][4];
            #pragma unroll
            for (int mf = 0; mf < 2; mf++) {
                int r = wm * 32 + mf * 16 + g;
                a[mf][0] = ldh2(&Qs[r * AT_STRH + k0 + 2 * c]);
                a[mf][1] = ldh2(&Qs[(r + 8) * AT_STRH + k0 + 2 * c]);
                a[mf][2] = ldh2(&Qs[r * AT_STRH + k0 + 2 * c + 8]);
                a[mf][3] = ldh2(&Qs[(r + 8) * AT_STRH + k0 + 2 * c + 8]);
            }
            #pragma unroll
            for (int nf = 0; nf < 2; nf++) {
                int n = wn * 16 + nf * 8 + g;
                uint32_t b0 = ldh2(&Kt[n * AT_STRH + k0 + 2 * c]);
                uint32_t b1 = ldh2(&Kt[n * AT_STRH + k0 + 2 * c + 8]);
                mma_f16(sfr[0][nf], a[0][0], a[0][1], a[0][2], a[0][3], b0, b1);
                mma_f16(sfr[1][nf], a[1][0], a[1][1], a[1][2], a[1][3], b0, b1);
            }
        }

        // Scale + causal mask + store fp32 scores
        bool needmask = (j0 + 64 > q0);
        #pragma unroll
        for (int mf = 0; mf < 2; mf++) {
            #pragma unroll
            for (int nf = 0; nf < 2; nf++) {
                int col = wn * 16 + nf * 8 + 2 * c;
                #pragma unroll
                for (int half_ = 0; half_ < 2; half_++) {
                    int row = wm * 32 + mf * 16 + g + half_ * 8;
                    int gi = q0 + row;
                    float v0 = sfr[mf][nf][2 * half_ + 0] * 0.125f;
                    float v1 = sfr[mf][nf][2 * half_ + 1] * 0.125f;
                    if (needmask) {
                        if (j0 + col > gi) v0 = -1e30f;
                        if (j0 + col + 1 > gi) v1 = -1e30f;
                    }
                    float2 sv; sv.x = v0; sv.y = v1;
                    *(float2*)&Ss[row * AT_STRS + col] = sv;
                }
            }
        }
        __syncthreads();

        // Online softmax: warp per row (16 warps x 8 rows). P -> half.
        #pragma unroll
        for (int rr = 0; rr < 8; rr++) {
            int row = wid * 8 + rr;
            float v0 = Ss[row * AT_STRS + lane];
            float v1 = Ss[row * AT_STRS + 32 + lane];
            float mx = fmaxf(v0, v1);
            #pragma unroll
            for (int off = 16; off > 0; off >>= 1)
                mx = fmaxf(mx, __shfl_xor_sync(0xffffffffu, mx, off));
            float mold = mrow[row];
            float mnew = fmaxf(mold, mx);
            __half hp0 = __float2half(__expf(v0 - mnew));
            __half hp1 = __float2half(__expf(v1 - mnew));
            Ps[row * AT_STRH + lane] = hp0;
            Ps[row * AT_STRH + 32 + lane] = hp1;
            float sum = __half2float(hp0) + __half2float(hp1);
            #pragma unroll
            for (int off = 16; off > 0; off >>= 1)
                sum += __shfl_xor_sync(0xffffffffu, sum, off);
            if (lane == 0) {
                float alpha = __expf(mold - mnew);
                arow[row] = alpha;
                lrow[row] = lrow[row] * alpha + sum;
                mrow[row] = mnew;
            }
        }
        __syncthreads();

        // O = O*alpha + P @ V   (V in smem as [d][j])
        #pragma unroll
        for (int mf = 0; mf < 2; mf++) {
            int r = wm * 32 + mf * 16 + g;
            float al0 = arow[r];
            float al1 = arow[r + 8];
            #pragma unroll
            for (int nf = 0; nf < 2; nf++) {
                ofr[mf][nf][0] *= al0;
                ofr[mf][nf][1] *= al0;
                ofr[mf][nf][2] *= al1;
                ofr[mf][nf][3] *= al1;
            }
        }

        #pragma unroll
        for (int kc = 0; kc < 4; kc++) {
            int k0 = kc * 16;
            uint32_t a[2][4];
            #pragma unroll
            for (int mf = 0; mf < 2; mf++) {
                int r = wm * 32 + mf * 16 + g;
                a[mf][0] = ldh2(&Ps[r * AT_STRH + k0 + 2 * c]);
                a[mf][1] = ldh2(&Ps[(r + 8) * AT_STRH + k0 + 2 * c]);
                a[mf][2] = ldh2(&Ps[r * AT_STRH + k0 + 2 * c + 8]);
                a[mf][3] = ldh2(&Ps[(r + 8) * AT_STRH + k0 + 2 * c + 8]);
            }
            #pragma unroll
            for (int nf = 0; nf < 2; nf++) {
                int n = wn * 16 + nf * 8 + g;      // n = d
                uint32_t b0 = ldh2(&Vt[n * AT_STRH + k0 + 2 * c]);
                uint32_t b1 = ldh2(&Vt[n * AT_STRH + k0 + 2 * c + 8]);
                mma_f16(ofr[0][nf], a[0][0], a[0][1], a[0][2], a[0][3], b0, b1);
                mma_f16(ofr[1][nf], a[1][0], a[1][1], a[1][2], a[1][3], b0, b1);
            }
        }
        __syncthreads();
    }

    // Finalize: divide by l, write ctx [B,S,H,D] half
    int b = bh >> 4, h = bh & 15;
    #pragma unroll
    for (int mf = 0; mf < 2; mf++) {
        #pragma unroll
        for (int half_ = 0; half_ < 2; half_++) {
            int row = wm * 32 + mf * 16 + g + half_ * 8;
            float inv = 1.f / lrow[row];
            size_t base = (((size_t)b * S_ + (q0 + row)) * H_ + h) * D_;
            #pragma unroll
            for (int nf = 0; nf < 2; nf++) {
                int col = wn * 16 + nf * 8 + 2 * c;
                __half2 res = __floats2half2_rn(
                    ofr[mf][nf][2 * half_ + 0] * inv,
                    ofr[mf][nf][2 * half_ + 1] * inv);
                *(__half2*)(o + base + col) = res;
            }
        }
    }
}

// ---------------------------------------------------------------------------
extern "C" void kernel_launch(void* const* d_in, const int* in_sizes, int n_in,
                              void* d_out, int out_size)
{
    const float* x  = (const float*)d_in[0];
    const float* Wq = (const float*)d_in[1];
    const float* bq = (const float*)d_in[2];
    const float* Wk = (const float*)d_in[3];
    const float* bk = (const float*)d_in[4];
    const float* Wv = (const float*)d_in[5];
    const float* bv = (const float*)d_in[6];
    const float* Wp = (const float*)d_in[7];
    const float* bp = (const float*)d_in[8];
    float* out = (float*)d_out;

    __half *xp, *qkvp, *op, *wqkvt, *wpt;
    float *bqkv;
    cudaGetSymbolAddress((void**)&xp, g_x);
    cudaGetSymbolAddress((void**)&qkvp, g_qkv);
    cudaGetSymbolAddress((void**)&op, g_o);
    cudaGetSymbolAddress((void**)&wqkvt, g_wqkvt);
    cudaGetSymbolAddress((void**)&wpt, g_wpt);
    cudaGetSymbolAddress((void**)&bqkv, g_bqkv);

    cudaFuncSetAttribute(attn_kernel,
                         cudaFuncAttributeMaxDynamicSharedMemorySize, ATTN_SMEM);
    cudaFuncSetAttribute(gemm_mma<0>,
                         cudaFuncAttributeMaxDynamicSharedMemorySize, GEMM_SMEM);
    cudaFuncSetAttribute(gemm_mma<1>,
                         cudaFuncAttributeMaxDynamicSharedMemorySize, GEMM_SMEM);

    // Pre-pass: convert x, transpose+convert weights, concat biases
    round_kernel<<<T_ * E_ / (256 * 8), 256>>>(x, xp);
    dim3 tb(32, 8);
    dim3 tgq(D_ / 32, E_ / 32, 48);
    transpose_qkv_kernel<<<tgq, tb>>>(Wq, Wk, Wv, wqkvt);
    dim3 tgp(HD_ / 32, E_ / 32, 1);   // wait: src rows = HD (R), cols = E (C)
    // transpose_wp: reads src[r in HD][c in E] tiles: grid.x over E cols, grid.y over HD rows
    dim3 tgp2(E_ / 32, HD_ / 32, 1);
    transpose_wp_kernel<<<tgp2, tb>>>(Wp, wpt);
    bias_kernel<<<12, 256>>>(bq, bk, bv, bqkv);

    // Fused QKV projection (fp16 mma), N = 3072
    dim3 gg(T_ / 128, 3 * HD_ / 128);                // 64 x 24
    gemm_mma<0><<<gg, 256, GEMM_SMEM>>>(xp, wqkvt, bqkv, qkvp);

    // Attention
    __half* qp = qkvp;
    __half* kp = qkvp + (size_t)T_ * HD_;
    __half* vp = qkvp + (size_t)2 * T_ * HD_;
    dim3 gattn(S_ / 128, B_ * H_);                   // 16 x 64
    attn_kernel<<<gattn, 512, ATTN_SMEM>>>(qp, kp, vp, op);

    // Output projection (fp16 mma, fp32 out)
    dim3 gp(T_ / 128, E_ / 128);                     // 64 x 8
    gemm_mma<1><<<gp, 256, GEMM_SMEM>>>(op, wpt, bp, out);
}

// round 6
// speedup vs baseline: 6.7751x; 1.7408x over previous
#include <cuda_runtime.h>
#include <cuda_fp16.h>
#include <cstdint>
#include <math.h>

#define B_  4
#define S_  2048
#define E_  1024
#define H_  16
#define D_  64
#define T_  (B_*S_)     // 8192 tokens
#define HD_ (H_*D_)     // 1024

// ---------------------------------------------------------------------------
// Scratch (static device arrays; no runtime allocation)
// ---------------------------------------------------------------------------
__device__ __half g_x[(size_t)T_*E_];          // fp16 x [T,E]
__device__ __half g_qkv[(size_t)3*T_*HD_];     // q|k|v, each [B,H,S,D]
__device__ __half g_o[(size_t)T_*HD_];         // ctx [B,S,H,D] == [T, HD]
__device__ __half g_wqkvt[(size_t)3*HD_*E_];   // K-major [n][e], q|k|v
__device__ __half g_wpt[(size_t)E_*HD_];       // K-major [n=e][c]
__device__ float  g_bqkv[3*HD_];               // concat bq|bk|bv (fp32)

// ---------------------------------------------------------------------------
// PTX helpers (plain sm_103-target-safe: mma.sync + ldmatrix + cp.async)
// ---------------------------------------------------------------------------
__device__ __forceinline__ uint32_t smem_u32(const void* p) {
    return (uint32_t)__cvta_generic_to_shared(p);
}
__device__ __forceinline__ void cp_async16(uint32_t dst, const void* src) {
    asm volatile("cp.async.cg.shared.global [%0], [%1], 16;\n" :: "r"(dst), "l"(src));
}
__device__ __forceinline__ void cp_commit() {
    asm volatile("cp.async.commit_group;\n" ::: "memory");
}
template<int N> __device__ __forceinline__ void cp_wait() {
    asm volatile("cp.async.wait_group %0;\n" :: "n"(N) : "memory");
}
__device__ __forceinline__ void mma_f16(float* c,
    uint32_t a0, uint32_t a1, uint32_t a2, uint32_t a3,
    uint32_t b0, uint32_t b1)
{
    asm volatile(
        "mma.sync.aligned.m16n8k16.row.col.f32.f16.f16.f32 "
        "{%0,%1,%2,%3},{%4,%5,%6,%7},{%8,%9},{%0,%1,%2,%3};"
        : "+f"(c[0]), "+f"(c[1]), "+f"(c[2]), "+f"(c[3])
        : "r"(a0), "r"(a1), "r"(a2), "r"(a3), "r"(b0), "r"(b1));
}
__device__ __forceinline__ void ldsm_x4(uint32_t* r, uint32_t a) {
    asm volatile("ldmatrix.sync.aligned.m8n8.x4.shared.b16 {%0,%1,%2,%3}, [%4];"
        : "=r"(r[0]), "=r"(r[1]), "=r"(r[2]), "=r"(r[3]) : "r"(a));
}
__device__ __forceinline__ void ldsm_x4t(uint32_t* r, uint32_t a) {
    asm volatile("ldmatrix.sync.aligned.m8n8.x4.trans.shared.b16 {%0,%1,%2,%3}, [%4];"
        : "=r"(r[0]), "=r"(r[1]), "=r"(r[2]), "=r"(r[3]) : "r"(a));
}

// ---------------------------------------------------------------------------
// Pre-pass kernels
// ---------------------------------------------------------------------------
__global__ void round_kernel(const float* __restrict__ src,
                             __half* __restrict__ dst)
{
    int i = (blockIdx.x * 256 + threadIdx.x) * 8;
    float4 v0 = *(const float4*)(src + i);
    float4 v1 = *(const float4*)(src + i + 4);
    __half2 h0 = __floats2half2_rn(v0.x, v0.y);
    __half2 h1 = __floats2half2_rn(v0.z, v0.w);
    __half2 h2 = __floats2half2_rn(v1.x, v1.y);
    __half2 h3 = __floats2half2_rn(v1.z, v1.w);
    uint4 st;
    st.x = *(uint32_t*)&h0; st.y = *(uint32_t*)&h1;
    st.z = *(uint32_t*)&h2; st.w = *(uint32_t*)&h3;
    *(uint4*)(dst + i) = st;
}

__global__ void transpose_qkv_kernel(const float* __restrict__ Wq,
                                     const float* __restrict__ Wk,
                                     const float* __restrict__ Wv,
                                     __half* __restrict__ dst)
{
    __shared__ float tile[32][33];
    int z = blockIdx.z;                 // 0..47 = sec*16 + h
    const float* W = (z < 16) ? Wq : (z < 32) ? Wk : Wv;
    const float* s = W + (size_t)(z & 15) * E_ * D_;
    __half* d = dst + (size_t)z * D_ * E_;
    int r0 = blockIdx.y * 32, c0 = blockIdx.x * 32;
    #pragma unroll
    for (int i = threadIdx.y; i < 32; i += 8)
        tile[i][threadIdx.x] = s[(size_t)(r0 + i) * D_ + c0 + threadIdx.x];
    __syncthreads();
    #pragma unroll
    for (int i = threadIdx.y; i < 32; i += 8)
        d[(size_t)(c0 + i) * E_ + r0 + threadIdx.x] =
            __float2half(tile[threadIdx.x][i]);
}

__global__ void transpose_wp_kernel(const float* __restrict__ src,
                                    __half* __restrict__ dst)
{
    __shared__ float tile[32][33];
    int r0 = blockIdx.y * 32, c0 = blockIdx.x * 32;
    #pragma unroll
    for (int i = threadIdx.y; i < 32; i += 8)
        tile[i][threadIdx.x] = src[(size_t)(r0 + i) * E_ + c0 + threadIdx.x];
    __syncthreads();
    #pragma unroll
    for (int i = threadIdx.y; i < 32; i += 8)
        dst[(size_t)(c0 + i) * HD_ + r0 + threadIdx.x] =
            __float2half(tile[threadIdx.x][i]);
}

__global__ void bias_kernel(const float* __restrict__ bq,
                            const float* __restrict__ bk,
                            const float* __restrict__ bv,
                            float* __restrict__ dst)
{
    int i = blockIdx.x * 256 + threadIdx.x;
    float v = (i < 1024) ? bq[i] : (i < 2048) ? bk[i - 1024] : bv[i - 2048];
    dst[i] = v;
}

// ---------------------------------------------------------------------------
// fp16 mma.sync GEMM with ldmatrix: out = A[8192,1024] x Bw^T (+bias)
// CTA 128x128, BK=32, 4-stage cp.async, 8 warps (4m x 2n), warp 32x64.
// MODE 0: fused QKV -> g_qkv (half, all [B,H,S,D]).  MODE 1: [T,E] fp32.
// ---------------------------------------------------------------------------
#define GEMM_BK     32
#define GEMM_STAGES 4
#define GEMM_KT     (E_ / GEMM_BK)           // 32
#define GEMM_STR    40                       // halfs per smem row (32+8 pad)
#define GEMM_TILEH  (128 * GEMM_STR)
#define GEMM_STAGEH (2 * GEMM_TILEH)
#define GEMM_SMEM   (GEMM_STAGES * GEMM_STAGEH * 2)    // 81920 B

__device__ __forceinline__ void gemm_load_stage(
    const __half* __restrict__ Ag, const __half* __restrict__ Bg,
    uint32_t abase, uint32_t bbase, int tid)
{
    #pragma unroll
    for (int j = 0; j < 2; j++) {
        int p = tid + j * 256;
        int r = p >> 2;                 // 0..127
        int ch = p & 3;                 // 0..3
        uint32_t off = (uint32_t)(r * (GEMM_STR * 2) + ch * 16);
        cp_async16(abase + off, Ag + (size_t)r * E_ + ch * 8);
        cp_async16(bbase + off, Bg + (size_t)r * E_ + ch * 8);
    }
}

template<int MODE>
__global__ __launch_bounds__(256, 2) void gemm_mma(
    const __half* __restrict__ A,
    const __half* __restrict__ Bw,
    const float* __restrict__ bias,
    void* __restrict__ outp)
{
    extern __shared__ __align__(16) __half smem[];
    uint32_t sb = smem_u32(smem);

    int tid = threadIdx.x;
    int wid = tid >> 5, lane = tid & 31;
    int g = lane >> 2, c = lane & 3;
    int lr = lane & 15, lc = lane >> 4;       // ldmatrix row / col-chunk
    int wm = wid & 3, wn = wid >> 2;          // 4 x 2 warp grid
    int m0 = blockIdx.x * 128;
    int n0 = blockIdx.y * 128;

    const __half* Abase = A + (size_t)m0 * E_;
    const __half* Bbase = Bw + (size_t)n0 * E_;

    float cfr[2][8][4];
    #pragma unroll
    for (int mf = 0; mf < 2; mf++)
        #pragma unroll
        for (int nf = 0; nf < 8; nf++)
            #pragma unroll
            for (int i = 0; i < 4; i++) cfr[mf][nf][i] = 0.f;

    #pragma unroll
    for (int s = 0; s < GEMM_STAGES - 1; s++) {
        gemm_load_stage(Abase + s * GEMM_BK, Bbase + s * GEMM_BK,
                        sb + s * GEMM_STAGEH * 2,
                        sb + (s * GEMM_STAGEH + GEMM_TILEH) * 2, tid);
        cp_commit();
    }

    for (int kt = 0; kt < GEMM_KT; kt++) {
        cp_wait<GEMM_STAGES - 2>();
        __syncthreads();

        int s = kt & (GEMM_STAGES - 1);
        uint32_t As_u = sb + s * GEMM_STAGEH * 2;
        uint32_t Bs_u = As_u + GEMM_TILEH * 2;

        #pragma unroll
        for (int kc = 0; kc < 2; kc++) {
            int k0 = kc * 16 + 8 * lc;
            uint32_t afr[2][4];
            #pragma unroll
            for (int mf = 0; mf < 2; mf++)
                ldsm_x4(afr[mf],
                    As_u + (uint32_t)((wm * 32 + mf * 16 + lr) * GEMM_STR + k0) * 2);
            #pragma unroll
            for (int np = 0; np < 4; np++) {
                uint32_t bfr[4];
                ldsm_x4(bfr,
                    Bs_u + (uint32_t)((wn * 64 + np * 16 + lr) * GEMM_STR + k0) * 2);
                // regs: [0]=n0-7 k0-7, [1]=n8-15 k0-7, [2]=n0-7 k8-15, [3]=n8-15 k8-15
                mma_f16(cfr[0][2*np+0], afr[0][0], afr[0][1], afr[0][2], afr[0][3], bfr[0], bfr[2]);
                mma_f16(cfr[1][2*np+0], afr[1][0], afr[1][1], afr[1][2], afr[1][3], bfr[0], bfr[2]);
                mma_f16(cfr[0][2*np+1], afr[0][0], afr[0][1], afr[0][2], afr[0][3], bfr[1], bfr[3]);
                mma_f16(cfr[1][2*np+1], afr[1][0], afr[1][1], afr[1][2], afr[1][3], bfr[1], bfr[3]);
            }
        }

        int ktn = kt + GEMM_STAGES - 1;
        if (ktn < GEMM_KT) {
            int sn = ktn & (GEMM_STAGES - 1);
            gemm_load_stage(Abase + ktn * GEMM_BK, Bbase + ktn * GEMM_BK,
                            sb + sn * GEMM_STAGEH * 2,
                            sb + (sn * GEMM_STAGEH + GEMM_TILEH) * 2, tid);
        }
        cp_commit();
    }

    // Epilogue
    #pragma unroll
    for (int mf = 0; mf < 2; mf++) {
        #pragma unroll
        for (int half_ = 0; half_ < 2; half_++) {
            int row = wm * 32 + mf * 16 + g + half_ * 8;
            int t = m0 + row;
            #pragma unroll
            for (int nf = 0; nf < 8; nf++) {
                int col = n0 + wn * 64 + nf * 8 + 2 * c;
                float vx = cfr[mf][nf][2 * half_ + 0] + bias[col];
                float vy = cfr[mf][nf][2 * half_ + 1] + bias[col + 1];
                if (MODE == 0) {
                    __half* ob = (__half*)outp + (size_t)(col >> 10) * ((size_t)T_ * HD_);
                    int cs = col & 1023;
                    int b = t >> 11, s_ = t & 2047;
                    int h = cs >> 6, d0 = cs & 63;
                    __half2 hv = __floats2half2_rn(vx, vy);
                    *(__half2*)(ob + (((size_t)(b * H_ + h)) * S_ + s_) * D_ + d0) = hv;
                } else {
                    float2 v; v.x = vx; v.y = vy;
                    *(float2*)((float*)outp + (size_t)t * E_ + col) = v;
                }
            }
        }
    }
}

// ---------------------------------------------------------------------------
// Flash attention, FA2-style register softmax. BQ=128, BKV=64, 256 threads.
// 8 warps, warp tile m16 x n64 (full rows per warp): no score/P smem.
// Q,K,V all [B,H,S,D] half; V consumed via ldmatrix.trans.
// ---------------------------------------------------------------------------
#define AT_STR 72          // halfs per smem row (64 + 8 pad)
#define ATTN_SMEM ((128 + 2*64 + 2*64) * AT_STR * 2)   // 55296 B

__global__ __launch_bounds__(256, 2) void attn_kernel(
    const __half* __restrict__ q,
    const __half* __restrict__ k,
    const __half* __restrict__ v,
    __half* __restrict__ o)
{
    extern __shared__ __align__(16) __half smh[];
    __half* Qs = smh;                        // [128][72]
    __half* Ks = Qs + 128 * AT_STR;          // [2][64][72]
    __half* Vs = Ks + 2 * 64 * AT_STR;       // [2][64][72]

    uint32_t Qs_u = smem_u32(Qs);
    uint32_t Ks_u = smem_u32(Ks);
    uint32_t Vs_u = smem_u32(Vs);

    int tid = threadIdx.x;
    int lane = tid & 31, wid = tid >> 5;     // 8 warps, warp = 16 q-rows
    int g = lane >> 2, c = lane & 3;
    int lr = lane & 15, lc = lane >> 4;
    int q0 = ((int)gridDim.x - 1 - (int)blockIdx.x) * 128;  // longest first
    int bh = blockIdx.y;

    const __half* qb = q + (size_t)bh * S_ * D_;
    const __half* kb = k + (size_t)bh * S_ * D_;
    const __half* vb = v + (size_t)bh * S_ * D_;

    // Q: 128 rows x 8 chunks = 1024; 256 thr -> 4 iters
    #pragma unroll
    for (int it = 0; it < 4; it++) {
        int p = tid + it * 256;
        int r = p >> 3, ch = p & 7;
        cp_async16(Qs_u + (uint32_t)(r * AT_STR + ch * 8) * 2,
                   qb + (size_t)(q0 + r) * D_ + ch * 8);
    }
    // K+V stage 0: 512+512 chunks -> 4 iters
    #pragma unroll
    for (int it = 0; it < 4; it++) {
        int p = tid + it * 256;
        int sel = p >> 9;
        int pp = p & 511;
        int r = pp >> 3, ch = pp & 7;
        uint32_t dst = (sel ? Vs_u : Ks_u) + (uint32_t)(r * AT_STR + ch * 8) * 2;
        const __half* src = (sel ? vb : kb) + (size_t)r * D_ + ch * 8;
        cp_async16(dst, src);
    }
    cp_commit();

    // Register state: stats + O accumulators (d = nf*8 + 2c, rows g / g+8)
    float m0r = -1e30f, m1r = -1e30f, l0 = 0.f, l1 = 0.f;
    float ofr[8][4];
    #pragma unroll
    for (int nf = 0; nf < 8; nf++)
        #pragma unroll
        for (int i = 0; i < 4; i++) ofr[nf][i] = 0.f;

    int ntiles = q0 / 64 + 2;
    int gi0 = q0 + wid * 16 + g;        // global q row (half 0); half 1 = +8

    for (int it = 0; it < ntiles; it++) {
        int j0 = it * 64;
        int st = it & 1;

        if (it + 1 < ntiles) {
            int j0n = j0 + 64;
            uint32_t kd = Ks_u + (uint32_t)((st ^ 1) * 64 * AT_STR) * 2;
            uint32_t vd = Vs_u + (uint32_t)((st ^ 1) * 64 * AT_STR) * 2;
            #pragma unroll
            for (int l = 0; l < 4; l++) {
                int p = tid + l * 256;
                int sel = p >> 9;
                int pp = p & 511;
                int r = pp >> 3, ch = pp & 7;
                uint32_t dst = (sel ? vd : kd) + (uint32_t)(r * AT_STR + ch * 8) * 2;
                const __half* src = (sel ? vb : kb) + (size_t)(j0n + r) * D_ + ch * 8;
                cp_async16(dst, src);
            }
        }
        cp_commit();
        cp_wait<1>();
        __syncthreads();

        uint32_t Kt_u = Ks_u + (uint32_t)(st * 64 * AT_STR) * 2;
        uint32_t Vt_u = Vs_u + (uint32_t)(st * 64 * AT_STR) * 2;

        // ---- S = Q @ K^T : m16 x n64 x k64 ----
        float sfr[8][4];
        #pragma unroll
        for (int nf = 0; nf < 8; nf++)
            #pragma unroll
            for (int i = 0; i < 4; i++) sfr[nf][i] = 0.f;

        #pragma unroll
        for (int kc = 0; kc < 4; kc++) {
            int k0 = kc * 16 + 8 * lc;
            uint32_t afr[4];
            ldsm_x4(afr, Qs_u + (uint32_t)((wid * 16 + lr) * AT_STR + k0) * 2);
            #pragma unroll
            for (int np = 0; np < 4; np++) {
                uint32_t bfr[4];
                ldsm_x4(bfr, Kt_u + (uint32_t)((np * 16 + lr) * AT_STR + k0) * 2);
                mma_f16(sfr[2*np+0], afr[0], afr[1], afr[2], afr[3], bfr[0], bfr[2]);
                mma_f16(sfr[2*np+1], afr[0], afr[1], afr[2], afr[3], bfr[1], bfr[3]);
            }
        }

        // ---- scale + causal mask (register) ----
        bool needmask = (j0 + 64 > q0);
        #pragma unroll
        for (int nf = 0; nf < 8; nf++) {
            int gj = j0 + nf * 8 + 2 * c;
            sfr[nf][0] *= 0.125f; sfr[nf][1] *= 0.125f;
            sfr[nf][2] *= 0.125f; sfr[nf][3] *= 0.125f;
            if (needmask) {
                if (gj     > gi0)     sfr[nf][0] = -1e30f;
                if (gj + 1 > gi0)     sfr[nf][1] = -1e30f;
                if (gj     > gi0 + 8) sfr[nf][2] = -1e30f;
                if (gj + 1 > gi0 + 8) sfr[nf][3] = -1e30f;
            }
        }

        // ---- online softmax in registers (quad reduce over c) ----
        float mx0 = -1e30f, mx1 = -1e30f;
        #pragma unroll
        for (int nf = 0; nf < 8; nf++) {
            mx0 = fmaxf(mx0, fmaxf(sfr[nf][0], sfr[nf][1]));
            mx1 = fmaxf(mx1, fmaxf(sfr[nf][2], sfr[nf][3]));
        }
        mx0 = fmaxf(mx0, __shfl_xor_sync(0xffffffffu, mx0, 1));
        mx0 = fmaxf(mx0, __shfl_xor_sync(0xffffffffu, mx0, 2));
        mx1 = fmaxf(mx1, __shfl_xor_sync(0xffffffffu, mx1, 1));
        mx1 = fmaxf(mx1, __shfl_xor_sync(0xffffffffu, mx1, 2));

        float mn0 = fmaxf(m0r, mx0);
        float mn1 = fmaxf(m1r, mx1);
        float al0 = __expf(m0r - mn0);
        float al1 = __expf(m1r - mn1);
        m0r = mn0; m1r = mn1;

        uint32_t ph0[8], ph1[8];   // P as half2 A-fragments (rows g / g+8)
        float sum0 = 0.f, sum1 = 0.f;
        #pragma unroll
        for (int nf = 0; nf < 8; nf++) {
            float p0 = __expf(sfr[nf][0] - mn0);
            float p1 = __expf(sfr[nf][1] - mn0);
            float p2 = __expf(sfr[nf][2] - mn1);
            float p3 = __expf(sfr[nf][3] - mn1);
            sum0 += p0 + p1;
            sum1 += p2 + p3;
            __half2 h01 = __floats2half2_rn(p0, p1);
            __half2 h23 = __floats2half2_rn(p2, p3);
            ph0[nf] = *(uint32_t*)&h01;
            ph1[nf] = *(uint32_t*)&h23;
        }
        sum0 += __shfl_xor_sync(0xffffffffu, sum0, 1);
        sum0 += __shfl_xor_sync(0xffffffffu, sum0, 2);
        sum1 += __shfl_xor_sync(0xffffffffu, sum1, 1);
        sum1 += __shfl_xor_sync(0xffffffffu, sum1, 2);
        l0 = l0 * al0 + sum0;
        l1 = l1 * al1 + sum1;

        // ---- O = O*alpha + P @ V (V via ldmatrix.trans; P from registers) ----
        #pragma unroll
        for (int nf = 0; nf < 8; nf++) {
            ofr[nf][0] *= al0; ofr[nf][1] *= al0;
            ofr[nf][2] *= al1; ofr[nf][3] *= al1;
        }
        #pragma unroll
        for (int kc = 0; kc < 4; kc++) {
            // A fragment (m16 k16) from P: k = j-cols kc*16..+15
            uint32_t a0 = ph0[2*kc],   a1 = ph1[2*kc];
            uint32_t a2 = ph0[2*kc+1], a3 = ph1[2*kc+1];
            #pragma unroll
            for (int np = 0; np < 4; np++) {
                uint32_t bfr[4];
                // rows j = kc*16 + lr, cols d = np*16 + 8*lc; trans -> B[n=d][k=j]
                ldsm_x4t(bfr, Vt_u +
                    (uint32_t)((kc * 16 + lr) * AT_STR + np * 16 + 8 * lc) * 2);
                // trans regs: [0]=b0(d0-7), [1]=b1(d0-7), [2]=b0(d8-15), [3]=b1(d8-15)
                mma_f16(ofr[2*np+0], a0, a1, a2, a3, bfr[0], bfr[1]);
                mma_f16(ofr[2*np+1], a0, a1, a2, a3, bfr[2], bfr[3]);
            }
        }
        __syncthreads();   // all warps done with stage st before it's refilled
    }

    // ---- finalize: /l, write ctx [B,S,H,D] half ----
    int b = bh >> 4, h = bh & 15;
    float inv0 = 1.f / l0, inv1 = 1.f / l1;
    int row0 = q0 + wid * 16 + g;
    size_t base0 = (((size_t)b * S_ + row0) * H_ + h) * D_;
    size_t base1 = (((size_t)b * S_ + row0 + 8) * H_ + h) * D_;
    #pragma unroll
    for (int nf = 0; nf < 8; nf++) {
        int col = nf * 8 + 2 * c;
        __half2 r0 = __floats2half2_rn(ofr[nf][0] * inv0, ofr[nf][1] * inv0);
        __half2 r1 = __floats2half2_rn(ofr[nf][2] * inv1, ofr[nf][3] * inv1);
        *(__half2*)(o + base0 + col) = r0;
        *(__half2*)(o + base1 + col) = r1;
    }
}

// ---------------------------------------------------------------------------
extern "C" void kernel_launch(void* const* d_in, const int* in_sizes, int n_in,
                              void* d_out, int out_size)
{
    const float* x  = (const float*)d_in[0];
    const float* Wq = (const float*)d_in[1];
    const float* bq = (const float*)d_in[2];
    const float* Wk = (const float*)d_in[3];
    const float* bk = (const float*)d_in[4];
    const float* Wv = (const float*)d_in[5];
    const float* bv = (const float*)d_in[6];
    const float* Wp = (const float*)d_in[7];
    const float* bp = (const float*)d_in[8];
    float* out = (float*)d_out;

    __half *xp, *qkvp, *op, *wqkvt, *wpt;
    float *bqkv;
    cudaGetSymbolAddress((void**)&xp, g_x);
    cudaGetSymbolAddress((void**)&qkvp, g_qkv);
    cudaGetSymbolAddress((void**)&op, g_o);
    cudaGetSymbolAddress((void**)&wqkvt, g_wqkvt);
    cudaGetSymbolAddress((void**)&wpt, g_wpt);
    cudaGetSymbolAddress((void**)&bqkv, g_bqkv);

    cudaFuncSetAttribute(attn_kernel,
                         cudaFuncAttributeMaxDynamicSharedMemorySize, ATTN_SMEM);
    cudaFuncSetAttribute(gemm_mma<0>,
                         cudaFuncAttributeMaxDynamicSharedMemorySize, GEMM_SMEM);
    cudaFuncSetAttribute(gemm_mma<1>,
                         cudaFuncAttributeMaxDynamicSharedMemorySize, GEMM_SMEM);

    round_kernel<<<T_ * E_ / (256 * 8), 256>>>(x, xp);
    dim3 tb(32, 8);
    dim3 tgq(D_ / 32, E_ / 32, 48);
    transpose_qkv_kernel<<<tgq, tb>>>(Wq, Wk, Wv, wqkvt);
    dim3 tgp(E_ / 32, HD_ / 32, 1);
    transpose_wp_kernel<<<tgp, tb>>>(Wp, wpt);
    bias_kernel<<<12, 256>>>(bq, bk, bv, bqkv);

    // Fused QKV projection, N = 3072
    dim3 gg(T_ / 128, 3 * HD_ / 128);                // 64 x 24
    gemm_mma<0><<<gg, 256, GEMM_SMEM>>>(xp, wqkvt, bqkv, qkvp);

    // Attention
    __half* qp = qkvp;
    __half* kp = qkvp + (size_t)T_ * HD_;
    __half* vp = qkvp + (size_t)2 * T_ * HD_;
    dim3 gattn(S_ / 128, B_ * H_);                   // 16 x 64
    attn_kernel<<<gattn, 256, ATTN_SMEM>>>(qp, kp, vp, op);

    // Output projection
    dim3 gp(T_ / 128, E_ / 128);                     // 64 x 8
    gemm_mma<1><<<gp, 256, GEMM_SMEM>>>(op, wpt, bp, out);
}